// round 4
// baseline (speedup 1.0000x reference)
#include <cuda_runtime.h>
#include <cstdint>

#define BN  2
#define NP  4096
#define KN  32
#define TOK 128
#define CQ  (BN*NP)
#define RAD2 (0.16f*0.16f)
#define H1S 144   // h1 smem row stride (uint), conflict-free LDS.128
#define PESS 48   // pes smem row stride

// Scratch (no allocations allowed)
__device__ float    g_F1 [CQ*TOK];   // feature @ W1[0:64]
__device__ float    g_A1b[CQ*TOK];   // abs_pe @ W1[91:187] + b1
__device__ int      g_idx[CQ*KN];
__device__ unsigned g_gmax[BN*TOK];

__device__ __forceinline__ unsigned f2ord(float f){
    unsigned u = __float_as_uint(f);
    return (u & 0x80000000u) ? ~u : (u | 0x80000000u);
}
__device__ __forceinline__ float ord2f(unsigned u){
    return __uint_as_float((u & 0x80000000u) ? (u ^ 0x80000000u) : ~u);
}
__device__ __forceinline__ unsigned tf32c(float f){
    unsigned u; asm("cvt.rna.tf32.f32 %0, %1;" : "=r"(u) : "f"(f)); return u;
}
// permuted column index: within each 16-col group, order so that an A-frag's
// {tig, tig+4} cols of two adjacent k8-tiles are 4 consecutive words
__device__ __host__ __forceinline__ int pcol(int c){
    int t = (c >> 3) & 1;
    int pos = 2*(c & 3) + ((c >> 2) & 1);
    return (c & ~15) + pos*2 + t;
}
__device__ __forceinline__ void mma8(float* c, unsigned a0, unsigned a1,
                                     unsigned a2, unsigned a3,
                                     unsigned b0, unsigned b1){
    asm volatile("mma.sync.aligned.m16n8k8.row.col.f32.tf32.tf32.f32 "
        "{%0,%1,%2,%3},{%4,%5,%6,%7},{%8,%9},{%0,%1,%2,%3};"
        : "+f"(c[0]), "+f"(c[1]), "+f"(c[2]), "+f"(c[3])
        : "r"(a0), "r"(a1), "r"(a2), "r"(a3), "r"(b0), "r"(b1));
}

// ---------------------------------------------------------------------------
// Fused setup: blocks [0, CQ) per-point precompute; blocks [CQ, CQ+CQ/4)
// ball query (4 query-warps per block). Overlaps the two independent stages.
// ---------------------------------------------------------------------------
__global__ __launch_bounds__(128)
void setup_kernel(const float* __restrict__ xyz,
                  const float* __restrict__ feat,
                  const float* __restrict__ W1,
                  const float* __restrict__ b1){
    if (blockIdx.x < CQ){
        // ---- precompute role: F1[row][c], A1b[row][c] ----
        int row = blockIdx.x;
        int c   = threadIdx.x;
        if (blockIdx.x == 0){ g_gmax[c] = 0u; g_gmax[128+c] = 0u; }
        __shared__ float sf[64], spe[96], sx[3];
        if (c < 3)  sx[c] = xyz[row*3 + c];
        if (c < 64) sf[c] = feat[row*64 + c];
        __syncthreads();
        if (c < 96){
            int a = c >> 5, t = c & 31, kk = t & 15;
            float f = __expf(-0.6140226914886731f * (float)kk);
            float ang = sx[a] * f;
            spe[c] = (t < 16) ? __sinf(ang) : __cosf(ang);
        }
        __syncthreads();
        float accF = 0.f;
        float accA = b1[c];
        #pragma unroll 16
        for (int d = 0; d < 64; d++) accF += sf[d]  * W1[d*TOK + c];
        #pragma unroll 16
        for (int d = 0; d < 96; d++) accA += spe[d] * W1[(91+d)*TOK + c];
        g_F1 [row*TOK + c] = accF;
        g_A1b[row*TOK + c] = accA;
    } else {
        // ---- neighbor role: first KN ascending idx with d2 <= r^2 ----
        int wl   = threadIdx.x >> 5;
        int lane = threadIdx.x & 31;
        int w    = (blockIdx.x - CQ)*4 + wl;     // query id
        int b = w >> 12, i = w & (NP-1);
        const float* xb = xyz + (size_t)b*NP*3;
        float cx = xb[i*3], cy = xb[i*3+1], cz = xb[i*3+2];
        __shared__ int s_idx[4][KN];
        int count = 0;
        for (int base = 0; base < NP && count < KN; base += 32){
            int j = base + lane;
            float dx = xb[j*3]   - cx;
            float dy = xb[j*3+1] - cy;
            float dz = xb[j*3+2] - cz;
            float d2 = dx*dx + dy*dy + dz*dz;
            bool hit = (d2 <= RAD2);
            unsigned m = __ballot_sync(0xFFFFFFFFu, hit);
            int pos = count + __popc(m & ((1u << lane) - 1u));
            if (hit && pos < KN) s_idx[wl][pos] = j;
            count += __popc(m);
        }
        __syncwarp();
        int stored = count < KN ? count : KN;
        int first  = s_idx[wl][0];
        int v = (lane < stored) ? s_idx[wl][lane] : first;
        g_idx[(size_t)w*KN + lane] = v;
    }
}

// ---------------------------------------------------------------------------
// Main kernel: 4 queries per iteration (128 rows), both layers via tf32 mma.
// W2/W1rel B-fragments held in registers; h1 staged in smem (permuted layout).
// 2 CTAs/SM for latency hiding.
// ---------------------------------------------------------------------------
__global__ __launch_bounds__(256, 2)
void main_kernel(const float* __restrict__ xyz,
                 const float* __restrict__ W1,
                 const float* __restrict__ W2){
    extern __shared__ unsigned char smraw[];
    unsigned* h1s  = (unsigned*)smraw;               // 128*144
    unsigned* pes  = h1s + 128*H1S;                  // 128*48
    float*    sA1b = (float*)(pes + 128*PESS);       // 4*128
    int*      sj   = (int*)(sA1b + 4*TOK);           // 4*32
    unsigned* sbmax= (unsigned*)(sj + 4*KN);         // 2*128

    const int tid  = threadIdx.x;
    const int w    = tid >> 5;
    const int lane = tid & 31;
    const int g    = lane >> 2;
    const int tig  = lane & 3;
    const int n0   = w * 16;

    sbmax[tid] = 0u;

    // B-fragments for W2 (16 k-tiles x 2 n-tiles) and W1rel (4 k-tiles, K pad 32)
    unsigned bw2[16][2][2];
    #pragma unroll
    for (int kt = 0; kt < 16; kt++)
        #pragma unroll
        for (int nt = 0; nt < 2; nt++){
            int col = n0 + nt*8 + g;
            bw2[kt][nt][0] = tf32c(W2[(kt*8 + tig    )*TOK + col]);
            bw2[kt][nt][1] = tf32c(W2[(kt*8 + tig + 4)*TOK + col]);
        }
    unsigned bw1[4][2][2];
    #pragma unroll
    for (int kt = 0; kt < 4; kt++)
        #pragma unroll
        for (int nt = 0; nt < 2; nt++){
            int col = n0 + nt*8 + g;
            int k0 = kt*8 + tig, k1 = k0 + 4;
            bw1[kt][nt][0] = (k0 < 27) ? tf32c(W1[(64+k0)*TOK + col]) : 0u;
            bw1[kt][nt][1] = (k1 < 27) ? tf32c(W1[(64+k1)*TOK + col]) : 0u;
        }
    // h1 store positions (constant per lane)
    int pc[2][2];
    #pragma unroll
    for (int nt = 0; nt < 2; nt++){
        int c0 = n0 + nt*8 + 2*tig;
        pc[nt][0] = pcol(c0); pc[nt][1] = pcol(c0+1);
    }

    for (int it = blockIdx.x; it < CQ/4; it += gridDim.x){
        int q0 = it * 4;
        int b  = q0 >> 12;
        const float* xb = xyz + (size_t)b*NP*3;
        const float* f1b = g_F1 + (size_t)b*NP*TOK;
        __syncthreads();   // h1s (prev phase B) + pes/sA1b free

        // ---- stage: sj, pes (tf32, permuted), sA1b ----
        if (tid < 128){
            int r = tid, qq = r >> 5, k = r & 31;
            int q = q0 + qq, i = q & (NP-1);
            int j = g_idx[q*KN + k];
            sj[qq*KN + k] = j;
            float ix = xb[i*3], iy = xb[i*3+1], iz = xb[i*3+2];
            float rx = xb[j*3]-ix, ry = xb[j*3+1]-iy, rz = xb[j*3+2]-iz;
            unsigned* pr = pes + r*PESS;
            pr[pcol(0)] = tf32c(rx);
            pr[pcol(1)] = tf32c(ry);
            pr[pcol(2)] = tf32c(rz);
            float rv[3] = {rx, ry, rz};
            const float fr[4] = {1.0f, 0.046415888336127795f,
                                 0.0021544346900318843f, 1.0e-4f};
            #pragma unroll
            for (int a = 0; a < 3; a++)
                #pragma unroll
                for (int f = 0; f < 4; f++){
                    float s, c2;
                    __sincosf(rv[a]*fr[f], &s, &c2);
                    pr[pcol(3 + a*8 + f)]     = tf32c(s);
                    pr[pcol(3 + a*8 + 4 + f)] = tf32c(c2);
                }
            #pragma unroll
            for (int d = 27; d < 32; d++) pr[pcol(d)] = 0u;
        } else {
            int t2 = tid - 128;
            int qq = t2 >> 5, e = (t2 & 31)*4;
            float4 v = *(const float4*)&g_A1b[(size_t)(q0+qq)*TOK + e];
            *(float4*)&sA1b[qq*TOK + e] = v;
        }
        __syncthreads();

        // ---- phase A: h1 = relu(pes@W1rel + F1[j] + A1b[i]) ----
        #pragma unroll 1
        for (int m = 0; m < 8; m++){
            const unsigned* pr0 = pes + (m*16 + g)*PESS;
            const unsigned* pr1 = pr0 + 8*PESS;
            uint4 lo0 = *(const uint4*)(pr0 + 4*tig);
            uint4 hi0 = *(const uint4*)(pr1 + 4*tig);
            uint4 lo1 = *(const uint4*)(pr0 + 16 + 4*tig);
            uint4 hi1 = *(const uint4*)(pr1 + 16 + 4*tig);
            int r0 = m*16 + g, r1 = r0 + 8, qq = m >> 1;
            int j0 = sj[qq*KN + (r0 & 31)];
            int j1 = sj[qq*KN + (r1 & 31)];
            float2 f1v[2][2], a1v[2];
            #pragma unroll
            for (int nt = 0; nt < 2; nt++){
                int c0 = n0 + nt*8 + 2*tig;
                f1v[nt][0] = *(const float2*)&f1b[(size_t)j0*TOK + c0];
                f1v[nt][1] = *(const float2*)&f1b[(size_t)j1*TOK + c0];
                a1v[nt]    = *(const float2*)&sA1b[qq*TOK + c0];
            }
            float acc[2][4] = {{0,0,0,0},{0,0,0,0}};
            #pragma unroll
            for (int nt = 0; nt < 2; nt++){
                mma8(acc[nt], lo0.x, hi0.x, lo0.z, hi0.z, bw1[0][nt][0], bw1[0][nt][1]);
                mma8(acc[nt], lo0.y, hi0.y, lo0.w, hi0.w, bw1[1][nt][0], bw1[1][nt][1]);
                mma8(acc[nt], lo1.x, hi1.x, lo1.z, hi1.z, bw1[2][nt][0], bw1[2][nt][1]);
                mma8(acc[nt], lo1.y, hi1.y, lo1.w, hi1.w, bw1[3][nt][0], bw1[3][nt][1]);
            }
            #pragma unroll
            for (int nt = 0; nt < 2; nt++){
                float v00 = fmaxf(acc[nt][0] + f1v[nt][0].x + a1v[nt].x, 0.f);
                float v01 = fmaxf(acc[nt][1] + f1v[nt][0].y + a1v[nt].y, 0.f);
                float v10 = fmaxf(acc[nt][2] + f1v[nt][1].x + a1v[nt].x, 0.f);
                float v11 = fmaxf(acc[nt][3] + f1v[nt][1].y + a1v[nt].y, 0.f);
                h1s[r0*H1S + pc[nt][0]] = tf32c(v00);
                h1s[r0*H1S + pc[nt][1]] = tf32c(v01);
                h1s[r1*H1S + pc[nt][0]] = tf32c(v10);
                h1s[r1*H1S + pc[nt][1]] = tf32c(v11);
            }
        }
        __syncthreads();

        // ---- phase B: h2 = h1 @ W2, then max over rows of each query ----
        #pragma unroll 1
        for (int m = 0; m < 8; m++){
            const unsigned* a0p = h1s + (m*16 + g)*H1S;
            const unsigned* a1p = a0p + 8*H1S;
            float acc[2][4] = {{0,0,0,0},{0,0,0,0}};
            #pragma unroll
            for (int kp = 0; kp < 8; kp++){
                uint4 lo = *(const uint4*)(a0p + kp*16 + 4*tig);
                uint4 hi = *(const uint4*)(a1p + kp*16 + 4*tig);
                #pragma unroll
                for (int nt = 0; nt < 2; nt++){
                    mma8(acc[nt], lo.x, hi.x, lo.z, hi.z,
                         bw2[2*kp  ][nt][0], bw2[2*kp  ][nt][1]);
                    mma8(acc[nt], lo.y, hi.y, lo.w, hi.w,
                         bw2[2*kp+1][nt][0], bw2[2*kp+1][nt][1]);
                }
            }
            #pragma unroll
            for (int nt = 0; nt < 2; nt++){
                float m0 = fmaxf(acc[nt][0], acc[nt][2]);  // col 2*tig
                float m1 = fmaxf(acc[nt][1], acc[nt][3]);  // col 2*tig+1
                #pragma unroll
                for (int off = 16; off >= 4; off >>= 1){
                    m0 = fmaxf(m0, __shfl_xor_sync(0xFFFFFFFFu, m0, off));
                    m1 = fmaxf(m1, __shfl_xor_sync(0xFFFFFFFFu, m1, off));
                }
                if (lane < 4){
                    int c0 = n0 + nt*8 + 2*tig;
                    atomicMax(&sbmax[b*TOK + c0    ], f2ord(m0));
                    atomicMax(&sbmax[b*TOK + c0 + 1], f2ord(m1));
                }
            }
        }
    }
    __syncthreads();
    atomicMax(&g_gmax[tid], sbmax[tid]);
}

// ---------------------------------------------------------------------------
// Final: g = max + b2 ; g = relu(g@W3+b3) ; out = g@W4+b4   (fp32)
// 512 threads: d-loop split 4 ways, smem partial reduction.
// ---------------------------------------------------------------------------
__global__ __launch_bounds__(512)
void final_kernel(const float* __restrict__ b2,
                  const float* __restrict__ W3,
                  const float* __restrict__ b3,
                  const float* __restrict__ W4,
                  const float* __restrict__ b4,
                  float* __restrict__ out){
    int b = blockIdx.x;
    int c = threadIdx.x & 127, p = threadIdx.x >> 7;   // p in 0..3
    __shared__ float gbuf[TOK], hbuf[TOK], part[4][TOK];
    if (p == 0) gbuf[c] = ord2f(g_gmax[b*TOK + c]) + b2[c];
    __syncthreads();
    float acc = 0.f;
    #pragma unroll 8
    for (int d = p*32; d < p*32 + 32; d++) acc += gbuf[d] * W3[d*TOK + c];
    part[p][c] = acc;
    __syncthreads();
    if (p == 0)
        hbuf[c] = fmaxf(part[0][c]+part[1][c]+part[2][c]+part[3][c]+b3[c], 0.f);
    __syncthreads();
    acc = 0.f;
    #pragma unroll 8
    for (int d = p*32; d < p*32 + 32; d++) acc += hbuf[d] * W4[d*TOK + c];
    part[p][c] = acc;
    __syncthreads();
    if (p == 0)
        out[b*TOK + c] = part[0][c]+part[1][c]+part[2][c]+part[3][c]+b4[c];
}

// ---------------------------------------------------------------------------
extern "C" void kernel_launch(void* const* d_in, const int* in_sizes, int n_in,
                              void* d_out, int out_size){
    const float* xyz  = (const float*)d_in[0];
    const float* feat = (const float*)d_in[1];
    const float* W1   = (const float*)d_in[2];
    const float* b1   = (const float*)d_in[3];
    const float* W2   = (const float*)d_in[4];
    const float* b2   = (const float*)d_in[5];
    const float* W3   = (const float*)d_in[6];
    const float* b3   = (const float*)d_in[7];
    const float* W4   = (const float*)d_in[8];
    const float* b4   = (const float*)d_in[9];
    float* out = (float*)d_out;

    const int MAIN_SMEM = (128*H1S + 128*PESS)*4 + 4*TOK*4 + 4*KN*4 + BN*TOK*4;
    cudaFuncSetAttribute(main_kernel,
                         cudaFuncAttributeMaxDynamicSharedMemorySize, MAIN_SMEM);

    setup_kernel<<<CQ + CQ/4, 128>>>(xyz, feat, W1, b1);
    main_kernel<<<296, 256, MAIN_SMEM>>>(xyz, W1, W2);
    final_kernel<<<BN, 512>>>(b2, W3, b3, W4, b4, out);
}

// round 7
// speedup vs baseline: 1.2331x; 1.2331x over previous
#include <cuda_runtime.h>
#include <cstdint>

#define BN  2
#define NP  4096
#define KN  32
#define TOK 128
#define CQ  (BN*NP)
#define RAD2 (0.16f*0.16f)
#define H1S 144   // h1 smem row stride (uint), conflict-free LDS.128
#define PESS 48   // pes smem row stride

// Scratch (no allocations allowed)
__device__ float    g_F1 [CQ*TOK];   // feature @ W1[0:64]
__device__ float    g_A1b[CQ*TOK];   // abs_pe @ W1[91:187] + b1
__device__ int      g_idx[CQ*KN];
__device__ unsigned g_gmax[BN*TOK];
__device__ float    g_x[CQ], g_y[CQ], g_z[CQ];   // SoA xyz

__device__ __forceinline__ unsigned f2ord(float f){
    unsigned u = __float_as_uint(f);
    return (u & 0x80000000u) ? ~u : (u | 0x80000000u);
}
__device__ __forceinline__ float ord2f(unsigned u){
    return __uint_as_float((u & 0x80000000u) ? (u ^ 0x80000000u) : ~u);
}
__device__ __forceinline__ unsigned tf32c(float f){
    unsigned u; asm("cvt.rna.tf32.f32 %0, %1;" : "=r"(u) : "f"(f)); return u;
}
// permuted column index (validated in R2/R3)
__device__ __host__ __forceinline__ int pcol(int c){
    int t = (c >> 3) & 1;
    int pos = 2*(c & 3) + ((c >> 2) & 1);
    return (c & ~15) + pos*2 + t;
}
__device__ __forceinline__ void mma8(float* c, unsigned a0, unsigned a1,
                                     unsigned a2, unsigned a3,
                                     unsigned b0, unsigned b1){
    asm volatile("mma.sync.aligned.m16n8k8.row.col.f32.tf32.tf32.f32 "
        "{%0,%1,%2,%3},{%4,%5,%6,%7},{%8,%9},{%0,%1,%2,%3};"
        : "+f"(c[0]), "+f"(c[1]), "+f"(c[2]), "+f"(c[3])
        : "r"(a0), "r"(a1), "r"(a2), "r"(a3), "r"(b0), "r"(b1));
}

// ---------------------------------------------------------------------------
// Transpose xyz AoS -> SoA, init g_gmax
// ---------------------------------------------------------------------------
__global__ void transpose_kernel(const float* __restrict__ xyz){
    int i = blockIdx.x*blockDim.x + threadIdx.x;
    if (i < CQ){
        g_x[i] = xyz[i*3];
        g_y[i] = xyz[i*3+1];
        g_z[i] = xyz[i*3+2];
    }
    if (i < BN*TOK) g_gmax[i] = 0u;
}

// ---------------------------------------------------------------------------
// Precompute (weight-stationary): W1 rows [0:64) + [91:187) in smem once per
// block; grid-stride over point groups of 4. Each W1 read serves 2 rows.
// ---------------------------------------------------------------------------
__global__ __launch_bounds__(256)
void precompute_kernel(const float* __restrict__ xyz,
                       const float* __restrict__ feat,
                       const float* __restrict__ W1,
                       const float* __restrict__ b1){
    extern __shared__ float psm[];
    float* W1f = psm;                 // 64*128
    float* W1a = W1f + 64*TOK;        // 96*128
    float* b1s = W1a + 96*TOK;        // 128
    float* sfb = b1s + TOK;           // 4*64
    float* spb = sfb + 4*64;          // 4*96
    float* sx  = spb + 4*96;          // 12
    const int tid = threadIdx.x;

    for (int t = tid; t < 64*TOK/4; t += 256)
        ((float4*)W1f)[t] = ((const float4*)W1)[t];
    for (int t = tid; t < 96*TOK/4; t += 256)
        ((float4*)W1a)[t] = ((const float4*)(W1 + 91*TOK))[t];
    if (tid < TOK) b1s[tid] = b1[tid];

    const int c  = tid & 127;
    const int ph = tid >> 7;       // 0..1 -> rows {2ph, 2ph+1}

    for (int rr = blockIdx.x; rr < CQ/4; rr += gridDim.x){
        int r0 = rr*4;
        __syncthreads();
        if (tid < 12) sx[tid] = xyz[r0*3 + tid];
        {   // sf: 4 rows x 64 (256 threads cover exactly)
            int p = tid >> 6, d = tid & 63;
            sfb[p*64 + d] = feat[(size_t)(r0+p)*64 + d];
        }
        __syncthreads();
        // spe: 4 rows x 96 = 384 entries
        for (int t = tid; t < 384; t += 256){
            int p = t / 96, cc = t % 96;
            int a = cc >> 5, kk = (cc & 31) & 15;
            float f = __expf(-0.6140226914886731f * (float)kk);
            float ang = sx[p*3 + a] * f;
            spb[p*96 + cc] = ((cc & 31) < 16) ? __sinf(ang) : __cosf(ang);
        }
        __syncthreads();
        float aF0 = 0.f, aF1 = 0.f;
        float aA0 = b1s[c], aA1 = aA0;
        const float* sf0 = sfb + (2*ph  )*64;
        const float* sf1 = sfb + (2*ph+1)*64;
        const float* sp0 = spb + (2*ph  )*96;
        const float* sp1 = spb + (2*ph+1)*96;
        #pragma unroll 16
        for (int d = 0; d < 64; d++){
            float wv = W1f[d*TOK + c];
            aF0 += sf0[d] * wv;
            aF1 += sf1[d] * wv;
        }
        #pragma unroll 16
        for (int d = 0; d < 96; d++){
            float wv = W1a[d*TOK + c];
            aA0 += sp0[d] * wv;
            aA1 += sp1[d] * wv;
        }
        g_F1 [(size_t)(r0+2*ph  )*TOK + c] = aF0;
        g_F1 [(size_t)(r0+2*ph+1)*TOK + c] = aF1;
        g_A1b[(size_t)(r0+2*ph  )*TOK + c] = aA0;
        g_A1b[(size_t)(r0+2*ph+1)*TOK + c] = aA1;
    }
}

// ---------------------------------------------------------------------------
// Ball query (SoA): first KN ascending indices with d2 <= r^2
// ---------------------------------------------------------------------------
__global__ __launch_bounds__(256)
void neighbor_kernel(){
    int gtid = blockIdx.x*blockDim.x + threadIdx.x;
    int w    = gtid >> 5;
    int lane = threadIdx.x & 31;
    if (w >= CQ) return;
    int b = w >> 12, i = w & (NP-1);
    const float* xs = g_x + (size_t)b*NP;
    const float* ys = g_y + (size_t)b*NP;
    const float* zs = g_z + (size_t)b*NP;
    float cx = xs[i], cy = ys[i], cz = zs[i];
    __shared__ int s_idx[8][KN];
    int wl = threadIdx.x >> 5;
    int count = 0;
    for (int base = 0; base < NP && count < KN; base += 32){
        int j = base + lane;
        float dx = xs[j]-cx, dy = ys[j]-cy, dz = zs[j]-cz;
        float d2 = dx*dx + dy*dy + dz*dz;
        bool hit = (d2 <= RAD2);
        unsigned m = __ballot_sync(0xFFFFFFFFu, hit);
        int pos = count + __popc(m & ((1u << lane) - 1u));
        if (hit && pos < KN) s_idx[wl][pos] = j;
        count += __popc(m);
    }
    __syncwarp();
    int stored = count < KN ? count : KN;
    int first  = s_idx[wl][0];
    int v = (lane < stored) ? s_idx[wl][lane] : first;
    g_idx[(size_t)w*KN + lane] = v;
}

// ---------------------------------------------------------------------------
// Main kernel: 512 threads, 8 queries (256 rows) per iter; each warp owns
// 8 output cols (B-frags 32+8 regs, no spills); both layers tf32 mma.
// ---------------------------------------------------------------------------
__global__ __launch_bounds__(512, 1)
void main_kernel(const float* __restrict__ W1,
                 const float* __restrict__ W2){
    extern __shared__ unsigned char smraw[];
    unsigned* h1s  = (unsigned*)smraw;               // 256*144
    unsigned* pes  = h1s + 256*H1S;                  // 256*48
    float*    sA1b = (float*)(pes + 256*PESS);       // 8*128
    int*      sj   = (int*)(sA1b + 8*TOK);           // 8*32
    unsigned* sbmax= (unsigned*)(sj + 8*KN);         // 2*128

    const int tid  = threadIdx.x;
    const int w    = tid >> 5;       // 0..15
    const int lane = tid & 31;
    const int g    = lane >> 2;
    const int tig  = lane & 3;
    const int n0   = w * 8;          // 8 cols per warp

    if (tid < BN*TOK) sbmax[tid] = 0u;

    // B-fragments: W2 16 k-tiles, W1rel 4 k-tiles (K padded to 32)
    unsigned bw2[16][2];
    {
        int col = n0 + g;
        #pragma unroll
        for (int kt = 0; kt < 16; kt++){
            bw2[kt][0] = tf32c(W2[(kt*8 + tig    )*TOK + col]);
            bw2[kt][1] = tf32c(W2[(kt*8 + tig + 4)*TOK + col]);
        }
    }
    unsigned bw1[4][2];
    {
        int col = n0 + g;
        #pragma unroll
        for (int kt = 0; kt < 4; kt++){
            int k0 = kt*8 + tig, k1 = k0 + 4;
            bw1[kt][0] = (k0 < 27) ? tf32c(W1[(64+k0)*TOK + col]) : 0u;
            bw1[kt][1] = (k1 < 27) ? tf32c(W1[(64+k1)*TOK + col]) : 0u;
        }
    }
    const int c0  = n0 + 2*tig;
    const int pc0 = pcol(c0), pc1 = pcol(c0+1);

    for (int it = blockIdx.x; it < CQ/8; it += gridDim.x){
        int q0 = it * 8;
        int b  = q0 >> 12;
        const float* f1b = g_F1 + (size_t)b*NP*TOK;
        const float* xs = g_x + (size_t)b*NP;
        const float* ys = g_y + (size_t)b*NP;
        const float* zs = g_z + (size_t)b*NP;
        __syncthreads();

        // ---- stage: sj, pes (256 rows, tf32 permuted), sA1b ----
        if (tid < 256){
            int r = tid, qq = r >> 5, k = r & 31;
            int q = q0 + qq, i = q & (NP-1);
            int j = g_idx[(size_t)q*KN + k];
            sj[qq*KN + k] = j;
            float rx = xs[j]-xs[i], ry = ys[j]-ys[i], rz = zs[j]-zs[i];
            unsigned* pr = pes + r*PESS;
            pr[pcol(0)] = tf32c(rx);
            pr[pcol(1)] = tf32c(ry);
            pr[pcol(2)] = tf32c(rz);
            float rv[3] = {rx, ry, rz};
            const float fr[4] = {1.0f, 0.046415888336127795f,
                                 0.0021544346900318843f, 1.0e-4f};
            #pragma unroll
            for (int a = 0; a < 3; a++)
                #pragma unroll
                for (int f = 0; f < 4; f++){
                    float s, cc;
                    __sincosf(rv[a]*fr[f], &s, &cc);
                    pr[pcol(3 + a*8 + f)]     = tf32c(s);
                    pr[pcol(3 + a*8 + 4 + f)] = tf32c(cc);
                }
            #pragma unroll
            for (int d = 27; d < 32; d++) pr[pcol(d)] = 0u;
        } else {
            int t2 = tid - 256;
            int qq = t2 >> 5, e = (t2 & 31)*4;
            float4 v = *(const float4*)&g_A1b[(size_t)(q0+qq)*TOK + e];
            *(float4*)&sA1b[qq*TOK + e] = v;
        }
        __syncthreads();

        // ---- phase A: h1 = relu(pes@W1rel + F1[j] + A1b[i]) ----
        #pragma unroll 1
        for (int m = 0; m < 16; m++){
            const unsigned* pr0 = pes + (m*16 + g)*PESS;
            const unsigned* pr1 = pr0 + 8*PESS;
            uint4 lo0 = *(const uint4*)(pr0 + 4*tig);
            uint4 hi0 = *(const uint4*)(pr1 + 4*tig);
            uint4 lo1 = *(const uint4*)(pr0 + 16 + 4*tig);
            uint4 hi1 = *(const uint4*)(pr1 + 16 + 4*tig);
            int r0 = m*16 + g, r1 = r0 + 8, qq = m >> 1;
            int j0 = sj[qq*KN + (r0 & 31)];
            int j1 = sj[qq*KN + (r1 & 31)];
            float2 f1v0 = *(const float2*)&f1b[(size_t)j0*TOK + c0];
            float2 f1v1 = *(const float2*)&f1b[(size_t)j1*TOK + c0];
            float2 a1v  = *(const float2*)&sA1b[qq*TOK + c0];
            float acc[4] = {0,0,0,0};
            mma8(acc, lo0.x, hi0.x, lo0.z, hi0.z, bw1[0][0], bw1[0][1]);
            mma8(acc, lo0.y, hi0.y, lo0.w, hi0.w, bw1[1][0], bw1[1][1]);
            mma8(acc, lo1.x, hi1.x, lo1.z, hi1.z, bw1[2][0], bw1[2][1]);
            mma8(acc, lo1.y, hi1.y, lo1.w, hi1.w, bw1[3][0], bw1[3][1]);
            h1s[r0*H1S + pc0] = tf32c(fmaxf(acc[0] + f1v0.x + a1v.x, 0.f));
            h1s[r0*H1S + pc1] = tf32c(fmaxf(acc[1] + f1v0.y + a1v.y, 0.f));
            h1s[r1*H1S + pc0] = tf32c(fmaxf(acc[2] + f1v1.x + a1v.x, 0.f));
            h1s[r1*H1S + pc1] = tf32c(fmaxf(acc[3] + f1v1.y + a1v.y, 0.f));
        }
        __syncthreads();

        // ---- phase B: h2 = h1 @ W2 ; running max into sbmax ----
        #pragma unroll 1
        for (int m = 0; m < 16; m++){
            const unsigned* a0p = h1s + (m*16 + g)*H1S;
            const unsigned* a1p = a0p + 8*H1S;
            float acc[4] = {0,0,0,0};
            #pragma unroll
            for (int kp = 0; kp < 8; kp++){
                uint4 lo = *(const uint4*)(a0p + kp*16 + 4*tig);
                uint4 hi = *(const uint4*)(a1p + kp*16 + 4*tig);
                mma8(acc, lo.x, hi.x, lo.z, hi.z, bw2[2*kp  ][0], bw2[2*kp  ][1]);
                mma8(acc, lo.y, hi.y, lo.w, hi.w, bw2[2*kp+1][0], bw2[2*kp+1][1]);
            }
            float m0 = fmaxf(acc[0], acc[2]);
            float m1 = fmaxf(acc[1], acc[3]);
            #pragma unroll
            for (int off = 16; off >= 4; off >>= 1){
                m0 = fmaxf(m0, __shfl_xor_sync(0xFFFFFFFFu, m0, off));
                m1 = fmaxf(m1, __shfl_xor_sync(0xFFFFFFFFu, m1, off));
            }
            if (lane < 4){
                atomicMax(&sbmax[b*TOK + c0    ], f2ord(m0));
                atomicMax(&sbmax[b*TOK + c0 + 1], f2ord(m1));
            }
        }
    }
    __syncthreads();
    if (tid < BN*TOK) atomicMax(&g_gmax[tid], sbmax[tid]);
}

// ---------------------------------------------------------------------------
// Final: g = max + b2 ; g = relu(g@W3+b3) ; out = g@W4+b4   (fp32)
// ---------------------------------------------------------------------------
__global__ __launch_bounds__(512)
void final_kernel(const float* __restrict__ b2,
                  const float* __restrict__ W3,
                  const float* __restrict__ b3,
                  const float* __restrict__ W4,
                  const float* __restrict__ b4,
                  float* __restrict__ out){
    int b = blockIdx.x;
    int c = threadIdx.x & 127, p = threadIdx.x >> 7;   // p in 0..3
    __shared__ float gbuf[TOK], hbuf[TOK], part[4][TOK];
    if (p == 0) gbuf[c] = ord2f(g_gmax[b*TOK + c]) + b2[c];
    __syncthreads();
    float acc = 0.f;
    #pragma unroll 8
    for (int d = p*32; d < p*32 + 32; d++) acc += gbuf[d] * W3[d*TOK + c];
    part[p][c] = acc;
    __syncthreads();
    if (p == 0)
        hbuf[c] = fmaxf(part[0][c]+part[1][c]+part[2][c]+part[3][c]+b3[c], 0.f);
    __syncthreads();
    acc = 0.f;
    #pragma unroll 8
    for (int d = p*32; d < p*32 + 32; d++) acc += hbuf[d] * W4[d*TOK + c];
    part[p][c] = acc;
    __syncthreads();
    if (p == 0)
        out[b*TOK + c] = part[0][c]+part[1][c]+part[2][c]+part[3][c]+b4[c];
}

// ---------------------------------------------------------------------------
extern "C" void kernel_launch(void* const* d_in, const int* in_sizes, int n_in,
                              void* d_out, int out_size){
    const float* xyz  = (const float*)d_in[0];
    const float* feat = (const float*)d_in[1];
    const float* W1   = (const float*)d_in[2];
    const float* b1   = (const float*)d_in[3];
    const float* W2   = (const float*)d_in[4];
    const float* b2   = (const float*)d_in[5];
    const float* W3   = (const float*)d_in[6];
    const float* b3   = (const float*)d_in[7];
    const float* W4   = (const float*)d_in[8];
    const float* b4   = (const float*)d_in[9];
    float* out = (float*)d_out;

    const int PRE_SMEM  = (64*TOK + 96*TOK + TOK + 4*64 + 4*96 + 12)*4;
    const int MAIN_SMEM = (256*H1S + 256*PESS)*4 + 8*TOK*4 + 8*KN*4 + BN*TOK*4;
    cudaFuncSetAttribute(precompute_kernel,
                         cudaFuncAttributeMaxDynamicSharedMemorySize, PRE_SMEM);
    cudaFuncSetAttribute(main_kernel,
                         cudaFuncAttributeMaxDynamicSharedMemorySize, MAIN_SMEM);

    transpose_kernel<<<(CQ+1023)/1024, 1024>>>(xyz);
    precompute_kernel<<<296, 256, PRE_SMEM>>>(xyz, feat, W1, b1);
    neighbor_kernel<<<CQ/8, 256>>>();
    main_kernel<<<148, 512, MAIN_SMEM>>>(W1, W2);
    final_kernel<<<BN, 512>>>(b2, W3, b3, W4, b4, out);
}

// round 9
// speedup vs baseline: 1.2545x; 1.0174x over previous
#include <cuda_runtime.h>
#include <cstdint>

#define BN  2
#define NP  4096
#define KN  32
#define TOK 128
#define CQ  (BN*NP)
#define RAD2 (0.16f*0.16f)
#define H1S 144   // h1 smem row stride (uint), conflict-free LDS.128
#define PESS 48   // pes smem row stride

// Scratch (no allocations allowed)
__device__ float    g_F1 [CQ*TOK];   // feature @ W1[0:64]
__device__ float    g_A1b[CQ*TOK];   // abs_pe @ W1[91:187] + b1
__device__ int      g_idx[CQ*KN];
__device__ unsigned g_gmax[BN*TOK];
__device__ float    g_x[CQ], g_y[CQ], g_z[CQ];   // SoA xyz

__device__ __forceinline__ unsigned f2ord(float f){
    unsigned u = __float_as_uint(f);
    return (u & 0x80000000u) ? ~u : (u | 0x80000000u);
}
__device__ __forceinline__ float ord2f(unsigned u){
    return __uint_as_float((u & 0x80000000u) ? (u ^ 0x80000000u) : ~u);
}
__device__ __forceinline__ unsigned tf32c(float f){
    unsigned u; asm("cvt.rna.tf32.f32 %0, %1;" : "=r"(u) : "f"(f)); return u;
}
// permuted column index (validated R2-R6)
__device__ __host__ __forceinline__ int pcol(int c){
    int t = (c >> 3) & 1;
    int pos = 2*(c & 3) + ((c >> 2) & 1);
    return (c & ~15) + pos*2 + t;
}
__device__ __forceinline__ void mma8(float* c, unsigned a0, unsigned a1,
                                     unsigned a2, unsigned a3,
                                     unsigned b0, unsigned b1){
    asm volatile("mma.sync.aligned.m16n8k8.row.col.f32.tf32.tf32.f32 "
        "{%0,%1,%2,%3},{%4,%5,%6,%7},{%8,%9},{%0,%1,%2,%3};"
        : "+f"(c[0]), "+f"(c[1]), "+f"(c[2]), "+f"(c[3])
        : "r"(a0), "r"(a1), "r"(a2), "r"(a3), "r"(b0), "r"(b1));
}

// ---------------------------------------------------------------------------
// Transpose xyz AoS -> SoA, init g_gmax
// ---------------------------------------------------------------------------
__global__ void transpose_kernel(const float* __restrict__ xyz){
    int i = blockIdx.x*blockDim.x + threadIdx.x;
    if (i < CQ){
        g_x[i] = xyz[i*3];
        g_y[i] = xyz[i*3+1];
        g_z[i] = xyz[i*3+2];
    }
    if (i < BN*TOK) g_gmax[i] = 0u;
}

// ---------------------------------------------------------------------------
// Precompute (weight-stationary): W1 rows [0:64) + [91:187) in smem once per
// block; grid-stride over point groups of 4.
// ---------------------------------------------------------------------------
__global__ __launch_bounds__(256)
void precompute_kernel(const float* __restrict__ xyz,
                       const float* __restrict__ feat,
                       const float* __restrict__ W1,
                       const float* __restrict__ b1){
    extern __shared__ float psm[];
    float* W1f = psm;                 // 64*128
    float* W1a = W1f + 64*TOK;        // 96*128
    float* b1s = W1a + 96*TOK;        // 128
    float* sfb = b1s + TOK;           // 4*64
    float* spb = sfb + 4*64;          // 4*96
    float* sx  = spb + 4*96;          // 12
    const int tid = threadIdx.x;

    for (int t = tid; t < 64*TOK/4; t += 256)
        ((float4*)W1f)[t] = ((const float4*)W1)[t];
    for (int t = tid; t < 96*TOK/4; t += 256)
        ((float4*)W1a)[t] = ((const float4*)(W1 + 91*TOK))[t];
    if (tid < TOK) b1s[tid] = b1[tid];

    const int c  = tid & 127;
    const int ph = tid >> 7;       // 0..1 -> rows {2ph, 2ph+1}

    for (int rr = blockIdx.x; rr < CQ/4; rr += gridDim.x){
        int r0 = rr*4;
        __syncthreads();
        if (tid < 12) sx[tid] = xyz[r0*3 + tid];
        {   // sf: 4 rows x 64 (256 threads cover exactly)
            int p = tid >> 6, d = tid & 63;
            sfb[p*64 + d] = feat[(size_t)(r0+p)*64 + d];
        }
        __syncthreads();
        for (int t = tid; t < 384; t += 256){
            int p = t / 96, cc = t % 96;
            int a = cc >> 5, kk = (cc & 31) & 15;
            float f = __expf(-0.6140226914886731f * (float)kk);
            float ang = sx[p*3 + a] * f;
            spb[p*96 + cc] = ((cc & 31) < 16) ? __sinf(ang) : __cosf(ang);
        }
        __syncthreads();
        float aF0 = 0.f, aF1 = 0.f;
        float aA0 = b1s[c], aA1 = aA0;
        const float* sf0 = sfb + (2*ph  )*64;
        const float* sf1 = sfb + (2*ph+1)*64;
        const float* sp0 = spb + (2*ph  )*96;
        const float* sp1 = spb + (2*ph+1)*96;
        #pragma unroll 16
        for (int d = 0; d < 64; d++){
            float wv = W1f[d*TOK + c];
            aF0 += sf0[d] * wv;
            aF1 += sf1[d] * wv;
        }
        #pragma unroll 16
        for (int d = 0; d < 96; d++){
            float wv = W1a[d*TOK + c];
            aA0 += sp0[d] * wv;
            aA1 += sp1[d] * wv;
        }
        g_F1 [(size_t)(r0+2*ph  )*TOK + c] = aF0;
        g_F1 [(size_t)(r0+2*ph+1)*TOK + c] = aF1;
        g_A1b[(size_t)(r0+2*ph  )*TOK + c] = aA0;
        g_A1b[(size_t)(r0+2*ph+1)*TOK + c] = aA1;
    }
}

// ---------------------------------------------------------------------------
// Ball query (SoA): first KN ascending indices with d2 <= r^2
// ---------------------------------------------------------------------------
__global__ __launch_bounds__(256)
void neighbor_kernel(){
    int gtid = blockIdx.x*blockDim.x + threadIdx.x;
    int w    = gtid >> 5;
    int lane = threadIdx.x & 31;
    if (w >= CQ) return;
    int b = w >> 12, i = w & (NP-1);
    const float* xs = g_x + (size_t)b*NP;
    const float* ys = g_y + (size_t)b*NP;
    const float* zs = g_z + (size_t)b*NP;
    float cx = xs[i], cy = ys[i], cz = zs[i];
    __shared__ int s_idx[8][KN];
    int wl = threadIdx.x >> 5;
    int count = 0;
    for (int base = 0; base < NP && count < KN; base += 32){
        int j = base + lane;
        float dx = xs[j]-cx, dy = ys[j]-cy, dz = zs[j]-cz;
        float d2 = dx*dx + dy*dy + dz*dz;
        bool hit = (d2 <= RAD2);
        unsigned m = __ballot_sync(0xFFFFFFFFu, hit);
        int pos = count + __popc(m & ((1u << lane) - 1u));
        if (hit && pos < KN) s_idx[wl][pos] = j;
        count += __popc(m);
    }
    __syncwarp();
    int stored = count < KN ? count : KN;
    int first  = s_idx[wl][0];
    int v = (lane < stored) ? s_idx[wl][lane] : first;
    g_idx[(size_t)w*KN + lane] = v;
}

// ---------------------------------------------------------------------------
// Main kernel: 512 threads, 8 queries (256 rows) per iter.
// Phase A: each warp 8 cols, full k=32 (tf32 mma).
// Phase B: warp PAIRS own 16 cols; even warp k[0:64), odd k[64:128);
//          partials combined via smem + named barrier (halves A-LDS traffic).
// ---------------------------------------------------------------------------
__global__ __launch_bounds__(512, 1)
void main_kernel(const float* __restrict__ W1,
                 const float* __restrict__ W2){
    extern __shared__ unsigned char smraw[];
    unsigned* h1s  = (unsigned*)smraw;               // 256*144
    unsigned* pes  = h1s + 256*H1S;                  // 256*48
    float*    sA1b = (float*)(pes + 256*PESS);       // 8*128
    int*      sj   = (int*)(sA1b + 8*TOK);           // 8*32
    unsigned* sbmax= (unsigned*)(sj + 8*KN);         // 2*128
    float*    pairbuf = (float*)(sbmax + BN*TOK);    // 8 pairs * 2 * 256

    const int tid  = threadIdx.x;
    const int w    = tid >> 5;       // 0..15
    const int lane = tid & 31;
    const int g    = lane >> 2;
    const int tig  = lane & 3;

    if (tid < BN*TOK) sbmax[tid] = 0u;

    // ---- phase A mapping: 8 cols per warp, full k ----
    const int n0A = w * 8;
    unsigned bw1[4][2];
    {
        int col = n0A + g;
        #pragma unroll
        for (int kt = 0; kt < 4; kt++){
            int k0 = kt*8 + tig, k1 = k0 + 4;
            bw1[kt][0] = (k0 < 27) ? tf32c(W1[(64+k0)*TOK + col]) : 0u;
            bw1[kt][1] = (k1 < 27) ? tf32c(W1[(64+k1)*TOK + col]) : 0u;
        }
    }
    const int c0A = n0A + 2*tig;
    const int pc0 = pcol(c0A), pc1 = pcol(c0A+1);

    // ---- phase B mapping: pair p owns 16 cols; half = k-range ----
    const int p    = w >> 1;
    const int half = w & 1;
    const int n0B  = p * 16;
    unsigned bw2[8][2][2];     // 8 local k-tiles (of this half) x 2 n-tiles
    #pragma unroll
    for (int ktl = 0; ktl < 8; ktl++)
        #pragma unroll
        for (int nt = 0; nt < 2; nt++){
            int col = n0B + nt*8 + g;
            int row = half*64 + ktl*8 + tig;
            bw2[ktl][nt][0] = tf32c(W2[(row    )*TOK + col]);
            bw2[ktl][nt][1] = tf32c(W2[(row + 4)*TOK + col]);
        }

    for (int it = blockIdx.x; it < CQ/8; it += gridDim.x){
        int q0 = it * 8;
        int b  = q0 >> 12;
        const float* f1b = g_F1 + (size_t)b*NP*TOK;
        const float* xs = g_x + (size_t)b*NP;
        const float* ys = g_y + (size_t)b*NP;
        const float* zs = g_z + (size_t)b*NP;
        __syncthreads();

        // ---- stage: sj, pes (256 rows, tf32 permuted), sA1b ----
        if (tid < 256){
            int r = tid, qq = r >> 5, k = r & 31;
            int q = q0 + qq, i = q & (NP-1);
            int j = g_idx[(size_t)q*KN + k];
            sj[qq*KN + k] = j;
            float rx = xs[j]-xs[i], ry = ys[j]-ys[i], rz = zs[j]-zs[i];
            unsigned* pr = pes + r*PESS;
            pr[pcol(0)] = tf32c(rx);
            pr[pcol(1)] = tf32c(ry);
            pr[pcol(2)] = tf32c(rz);
            float rv[3] = {rx, ry, rz};
            const float fr[4] = {1.0f, 0.046415888336127795f,
                                 0.0021544346900318843f, 1.0e-4f};
            #pragma unroll
            for (int a = 0; a < 3; a++)
                #pragma unroll
                for (int f = 0; f < 4; f++){
                    float s, cc;
                    __sincosf(rv[a]*fr[f], &s, &cc);
                    pr[pcol(3 + a*8 + f)]     = tf32c(s);
                    pr[pcol(3 + a*8 + 4 + f)] = tf32c(cc);
                }
            #pragma unroll
            for (int d = 27; d < 32; d++) pr[pcol(d)] = 0u;
        } else {
            int t2 = tid - 256;
            int qq = t2 >> 5, e = (t2 & 31)*4;
            float4 v = *(const float4*)&g_A1b[(size_t)(q0+qq)*TOK + e];
            *(float4*)&sA1b[qq*TOK + e] = v;
        }
        __syncthreads();

        // ---- phase A: h1 = relu(pes@W1rel + F1[j] + A1b[i]) ----
        #pragma unroll 1
        for (int m = 0; m < 16; m++){
            const unsigned* pr0 = pes + (m*16 + g)*PESS;
            const unsigned* pr1 = pr0 + 8*PESS;
            uint4 lo0 = *(const uint4*)(pr0 + 4*tig);
            uint4 hi0 = *(const uint4*)(pr1 + 4*tig);
            uint4 lo1 = *(const uint4*)(pr0 + 16 + 4*tig);
            uint4 hi1 = *(const uint4*)(pr1 + 16 + 4*tig);
            int r0 = m*16 + g, r1 = r0 + 8, qq = m >> 1;
            int j0 = sj[qq*KN + (r0 & 31)];
            int j1 = sj[qq*KN + (r1 & 31)];
            float2 f1v0 = *(const float2*)&f1b[(size_t)j0*TOK + c0A];
            float2 f1v1 = *(const float2*)&f1b[(size_t)j1*TOK + c0A];
            float2 a1v  = *(const float2*)&sA1b[qq*TOK + c0A];
            float acc[4] = {0,0,0,0};
            mma8(acc, lo0.x, hi0.x, lo0.z, hi0.z, bw1[0][0], bw1[0][1]);
            mma8(acc, lo0.y, hi0.y, lo0.w, hi0.w, bw1[1][0], bw1[1][1]);
            mma8(acc, lo1.x, hi1.x, lo1.z, hi1.z, bw1[2][0], bw1[2][1]);
            mma8(acc, lo1.y, hi1.y, lo1.w, hi1.w, bw1[3][0], bw1[3][1]);
            h1s[r0*H1S + pc0] = tf32c(fmaxf(acc[0] + f1v0.x + a1v.x, 0.f));
            h1s[r0*H1S + pc1] = tf32c(fmaxf(acc[1] + f1v0.y + a1v.y, 0.f));
            h1s[r1*H1S + pc0] = tf32c(fmaxf(acc[2] + f1v1.x + a1v.x, 0.f));
            h1s[r1*H1S + pc1] = tf32c(fmaxf(acc[3] + f1v1.y + a1v.y, 0.f));
        }
        __syncthreads();

        // ---- phase B: h2 = h1 @ W2, k split across warp pairs ----
        #pragma unroll 1
        for (int m = 0; m < 16; m++){
            const unsigned* a0p = h1s + (m*16 + g)*H1S + half*64;
            const unsigned* a1p = a0p + 8*H1S;
            float acc[2][4] = {{0,0,0,0},{0,0,0,0}};
            #pragma unroll
            for (int kpl = 0; kpl < 4; kpl++){
                uint4 lo = *(const uint4*)(a0p + kpl*16 + 4*tig);
                uint4 hi = *(const uint4*)(a1p + kpl*16 + 4*tig);
                #pragma unroll
                for (int nt = 0; nt < 2; nt++){
                    mma8(acc[nt], lo.x, hi.x, lo.z, hi.z,
                         bw2[2*kpl  ][nt][0], bw2[2*kpl  ][nt][1]);
                    mma8(acc[nt], lo.y, hi.y, lo.w, hi.w,
                         bw2[2*kpl+1][nt][0], bw2[2*kpl+1][nt][1]);
                }
            }
            float* buf = pairbuf + (p*2 + (m & 1))*256;
            if (half){
                float4* dst = (float4*)(buf + lane*8);
                dst[0] = make_float4(acc[0][0], acc[0][1], acc[0][2], acc[0][3]);
                dst[1] = make_float4(acc[1][0], acc[1][1], acc[1][2], acc[1][3]);
                asm volatile("bar.sync %0, 64;" :: "r"(p+1) : "memory");
            } else {
                asm volatile("bar.sync %0, 64;" :: "r"(p+1) : "memory");
                const float4* src = (const float4*)(buf + lane*8);
                float4 s0 = src[0], s1 = src[1];
                acc[0][0] += s0.x; acc[0][1] += s0.y;
                acc[0][2] += s0.z; acc[0][3] += s0.w;
                acc[1][0] += s1.x; acc[1][1] += s1.y;
                acc[1][2] += s1.z; acc[1][3] += s1.w;
                #pragma unroll
                for (int nt = 0; nt < 2; nt++){
                    float m0 = fmaxf(acc[nt][0], acc[nt][2]);
                    float m1 = fmaxf(acc[nt][1], acc[nt][3]);
                    #pragma unroll
                    for (int off = 16; off >= 4; off >>= 1){
                        m0 = fmaxf(m0, __shfl_xor_sync(0xFFFFFFFFu, m0, off));
                        m1 = fmaxf(m1, __shfl_xor_sync(0xFFFFFFFFu, m1, off));
                    }
                    if (lane < 4){
                        int cB = n0B + nt*8 + 2*tig;
                        atomicMax(&sbmax[b*TOK + cB    ], f2ord(m0));
                        atomicMax(&sbmax[b*TOK + cB + 1], f2ord(m1));
                    }
                }
            }
        }
    }
    __syncthreads();
    if (tid < BN*TOK) atomicMax(&g_gmax[tid], sbmax[tid]);
}

// ---------------------------------------------------------------------------
// Final: g = max + b2 ; g = relu(g@W3+b3) ; out = g@W4+b4   (fp32)
// ---------------------------------------------------------------------------
__global__ __launch_bounds__(512)
void final_kernel(const float* __restrict__ b2,
                  const float* __restrict__ W3,
                  const float* __restrict__ b3,
                  const float* __restrict__ W4,
                  const float* __restrict__ b4,
                  float* __restrict__ out){
    int b = blockIdx.x;
    int c = threadIdx.x & 127, p = threadIdx.x >> 7;   // p in 0..3
    __shared__ float gbuf[TOK], hbuf[TOK], part[4][TOK];
    if (p == 0) gbuf[c] = ord2f(g_gmax[b*TOK + c]) + b2[c];
    __syncthreads();
    float acc = 0.f;
    #pragma unroll 8
    for (int d = p*32; d < p*32 + 32; d++) acc += gbuf[d] * W3[d*TOK + c];
    part[p][c] = acc;
    __syncthreads();
    if (p == 0)
        hbuf[c] = fmaxf(part[0][c]+part[1][c]+part[2][c]+part[3][c]+b3[c], 0.f);
    __syncthreads();
    acc = 0.f;
    #pragma unroll 8
    for (int d = p*32; d < p*32 + 32; d++) acc += hbuf[d] * W4[d*TOK + c];
    part[p][c] = acc;
    __syncthreads();
    if (p == 0)
        out[b*TOK + c] = part[0][c]+part[1][c]+part[2][c]+part[3][c]+b4[c];
}

// ---------------------------------------------------------------------------
extern "C" void kernel_launch(void* const* d_in, const int* in_sizes, int n_in,
                              void* d_out, int out_size){
    const float* xyz  = (const float*)d_in[0];
    const float* feat = (const float*)d_in[1];
    const float* W1   = (const float*)d_in[2];
    const float* b1   = (const float*)d_in[3];
    const float* W2   = (const float*)d_in[4];
    const float* b2   = (const float*)d_in[5];
    const float* W3   = (const float*)d_in[6];
    const float* b3   = (const float*)d_in[7];
    const float* W4   = (const float*)d_in[8];
    const float* b4   = (const float*)d_in[9];
    float* out = (float*)d_out;

    const int PRE_SMEM  = (64*TOK + 96*TOK + TOK + 4*64 + 4*96 + 12)*4;
    const int MAIN_SMEM = (256*H1S + 256*PESS)*4 + 8*TOK*4 + 8*KN*4
                        + BN*TOK*4 + 8*2*256*4;
    cudaFuncSetAttribute(precompute_kernel,
                         cudaFuncAttributeMaxDynamicSharedMemorySize, PRE_SMEM);
    cudaFuncSetAttribute(main_kernel,
                         cudaFuncAttributeMaxDynamicSharedMemorySize, MAIN_SMEM);

    transpose_kernel<<<(CQ+1023)/1024, 1024>>>(xyz);
    precompute_kernel<<<296, 256, PRE_SMEM>>>(xyz, feat, W1, b1);
    neighbor_kernel<<<CQ/8, 256>>>();
    main_kernel<<<148, 512, MAIN_SMEM>>>(W1, W2);
    final_kernel<<<BN, 512>>>(b2, W3, b3, W4, b4, out);
}

// round 10
// speedup vs baseline: 1.4788x; 1.1787x over previous
#include <cuda_runtime.h>
#include <cstdint>

#define BN  2
#define NP  4096
#define KN  32
#define TOK 128
#define CQ  (BN*NP)
#define RAD2 (0.16f*0.16f)
#define H1S 144   // h1 smem row stride (words)
#define PESS 48   // pes smem row stride (words)

// Scratch (no allocations allowed)
__device__ float    g_F1 [CQ*TOK];   // feature @ W1[0:64]
__device__ float    g_A1b[CQ*TOK];   // abs_pe @ W1[91:187] + b1
__device__ int      g_idx[CQ*KN];
__device__ unsigned g_gmax[BN*TOK];
__device__ float    g_x[CQ], g_y[CQ], g_z[CQ];   // SoA xyz

__device__ __forceinline__ unsigned f2ord(float f){
    unsigned u = __float_as_uint(f);
    return (u & 0x80000000u) ? ~u : (u | 0x80000000u);
}
__device__ __forceinline__ float ord2f(unsigned u){
    return __uint_as_float((u & 0x80000000u) ? (u ^ 0x80000000u) : ~u);
}
__device__ __forceinline__ unsigned tf32c(float f){
    unsigned u; asm("cvt.rna.tf32.f32 %0, %1;" : "=r"(u) : "f"(f)); return u;
}
// permuted column index (validated R2-R8)
__device__ __host__ __forceinline__ int pcol(int c){
    int t = (c >> 3) & 1;
    int pos = 2*(c & 3) + ((c >> 2) & 1);
    return (c & ~15) + pos*2 + t;
}
__device__ __forceinline__ void mma8(float* c, unsigned a0, unsigned a1,
                                     unsigned a2, unsigned a3,
                                     unsigned b0, unsigned b1){
    asm volatile("mma.sync.aligned.m16n8k8.row.col.f32.tf32.tf32.f32 "
        "{%0,%1,%2,%3},{%4,%5,%6,%7},{%8,%9},{%0,%1,%2,%3};"
        : "+f"(c[0]), "+f"(c[1]), "+f"(c[2]), "+f"(c[3])
        : "r"(a0), "r"(a1), "r"(a2), "r"(a3), "r"(b0), "r"(b1));
}

// ---------------------------------------------------------------------------
// Transpose xyz AoS -> SoA, init g_gmax
// ---------------------------------------------------------------------------
__global__ void transpose_kernel(const float* __restrict__ xyz){
    int i = blockIdx.x*blockDim.x + threadIdx.x;
    if (i < CQ){
        g_x[i] = xyz[i*3];
        g_y[i] = xyz[i*3+1];
        g_z[i] = xyz[i*3+2];
    }
    if (i < BN*TOK) g_gmax[i] = 0u;
}

// ---------------------------------------------------------------------------
// Precompute (weight-stationary): W1 rows [0:64) + [91:187) in smem once per
// block; grid-stride over point groups of 4.
// ---------------------------------------------------------------------------
__global__ __launch_bounds__(256)
void precompute_kernel(const float* __restrict__ xyz,
                       const float* __restrict__ feat,
                       const float* __restrict__ W1,
                       const float* __restrict__ b1){
    extern __shared__ float psm[];
    float* W1f = psm;                 // 64*128
    float* W1a = W1f + 64*TOK;        // 96*128
    float* b1s = W1a + 96*TOK;        // 128
    float* sfb = b1s + TOK;           // 4*64
    float* spb = sfb + 4*64;          // 4*96
    float* sx  = spb + 4*96;          // 12
    const int tid = threadIdx.x;

    for (int t = tid; t < 64*TOK/4; t += 256)
        ((float4*)W1f)[t] = ((const float4*)W1)[t];
    for (int t = tid; t < 96*TOK/4; t += 256)
        ((float4*)W1a)[t] = ((const float4*)(W1 + 91*TOK))[t];
    if (tid < TOK) b1s[tid] = b1[tid];

    const int c  = tid & 127;
    const int ph = tid >> 7;       // 0..1 -> rows {2ph, 2ph+1}

    for (int rr = blockIdx.x; rr < CQ/4; rr += gridDim.x){
        int r0 = rr*4;
        __syncthreads();
        if (tid < 12) sx[tid] = xyz[r0*3 + tid];
        {   // sf: 4 rows x 64 (256 threads cover exactly)
            int p = tid >> 6, d = tid & 63;
            sfb[p*64 + d] = feat[(size_t)(r0+p)*64 + d];
        }
        __syncthreads();
        for (int t = tid; t < 384; t += 256){
            int p = t / 96, cc = t % 96;
            int a = cc >> 5, kk = (cc & 31) & 15;
            float f = __expf(-0.6140226914886731f * (float)kk);
            float ang = sx[p*3 + a] * f;
            spb[p*96 + cc] = ((cc & 31) < 16) ? __sinf(ang) : __cosf(ang);
        }
        __syncthreads();
        float aF0 = 0.f, aF1 = 0.f;
        float aA0 = b1s[c], aA1 = aA0;
        const float* sf0 = sfb + (2*ph  )*64;
        const float* sf1 = sfb + (2*ph+1)*64;
        const float* sp0 = spb + (2*ph  )*96;
        const float* sp1 = spb + (2*ph+1)*96;
        #pragma unroll 16
        for (int d = 0; d < 64; d++){
            float wv = W1f[d*TOK + c];
            aF0 += sf0[d] * wv;
            aF1 += sf1[d] * wv;
        }
        #pragma unroll 16
        for (int d = 0; d < 96; d++){
            float wv = W1a[d*TOK + c];
            aA0 += sp0[d] * wv;
            aA1 += sp1[d] * wv;
        }
        g_F1 [(size_t)(r0+2*ph  )*TOK + c] = aF0;
        g_F1 [(size_t)(r0+2*ph+1)*TOK + c] = aF1;
        g_A1b[(size_t)(r0+2*ph  )*TOK + c] = aA0;
        g_A1b[(size_t)(r0+2*ph+1)*TOK + c] = aA1;
    }
}

// ---------------------------------------------------------------------------
// Ball query (SoA): first KN ascending indices with d2 <= r^2
// ---------------------------------------------------------------------------
__global__ __launch_bounds__(256)
void neighbor_kernel(){
    int gtid = blockIdx.x*blockDim.x + threadIdx.x;
    int w    = gtid >> 5;
    int lane = threadIdx.x & 31;
    if (w >= CQ) return;
    int b = w >> 12, i = w & (NP-1);
    const float* xs = g_x + (size_t)b*NP;
    const float* ys = g_y + (size_t)b*NP;
    const float* zs = g_z + (size_t)b*NP;
    float cx = xs[i], cy = ys[i], cz = zs[i];
    __shared__ int s_idx[8][KN];
    int wl = threadIdx.x >> 5;
    int count = 0;
    for (int base = 0; base < NP && count < KN; base += 32){
        int j = base + lane;
        float dx = xs[j]-cx, dy = ys[j]-cy, dz = zs[j]-cz;
        float d2 = dx*dx + dy*dy + dz*dz;
        bool hit = (d2 <= RAD2);
        unsigned m = __ballot_sync(0xFFFFFFFFu, hit);
        int pos = count + __popc(m & ((1u << lane) - 1u));
        if (hit && pos < KN) s_idx[wl][pos] = j;
        count += __popc(m);
    }
    __syncwarp();
    int stored = count < KN ? count : KN;
    int first  = s_idx[wl][0];
    int v = (lane < stored) ? s_idx[wl][lane] : first;
    g_idx[(size_t)w*KN + lane] = v;
}

// ---------------------------------------------------------------------------
// Main kernel: 256 threads, 2 CTAs/SM. 4 queries (128 rows) per iter.
// 8 warps x 16 cols each (multiplicity 8 in both phases), full k, no exchange.
// XOR swizzle xr=(r&7)<<2 on pes & h1 word addressing:
//   stores <=4-way conflicted, all LDS.128 reads conflict-free.
// ---------------------------------------------------------------------------
__global__ __launch_bounds__(256, 2)
void main_kernel(const float* __restrict__ W1,
                 const float* __restrict__ W2){
    extern __shared__ unsigned char smraw[];
    unsigned* h1s  = (unsigned*)smraw;               // 128*144
    unsigned* pes  = h1s + 128*H1S;                  // 128*48
    float*    sA1b = (float*)(pes + 128*PESS);       // 4*128
    int*      sj   = (int*)(sA1b + 4*TOK);           // 4*32
    unsigned* sbmax= (unsigned*)(sj + 4*KN);         // 2*128

    const int tid  = threadIdx.x;
    const int w    = tid >> 5;       // 0..7
    const int lane = tid & 31;
    const int g    = lane >> 2;
    const int tig  = lane & 3;
    const int n0   = w * 16;         // 16 cols per warp
    const int xr   = g << 2;         // row-xor for this lane's rows (r&7 == g)

    sbmax[tid] = 0u;

    // B-fragments: W2 16 k-tiles x 2 n-tiles; W1rel 4 k-tiles x 2 n-tiles
    unsigned bw2[16][2][2];
    #pragma unroll
    for (int kt = 0; kt < 16; kt++)
        #pragma unroll
        for (int nt = 0; nt < 2; nt++){
            int col = n0 + nt*8 + g;
            bw2[kt][nt][0] = tf32c(W2[(kt*8 + tig    )*TOK + col]);
            bw2[kt][nt][1] = tf32c(W2[(kt*8 + tig + 4)*TOK + col]);
        }
    unsigned bw1[4][2][2];
    #pragma unroll
    for (int kt = 0; kt < 4; kt++)
        #pragma unroll
        for (int nt = 0; nt < 2; nt++){
            int col = n0 + nt*8 + g;
            int k0 = kt*8 + tig, k1 = k0 + 4;
            bw1[kt][nt][0] = (k0 < 27) ? tf32c(W1[(64+k0)*TOK + col]) : 0u;
            bw1[kt][nt][1] = (k1 < 27) ? tf32c(W1[(64+k1)*TOK + col]) : 0u;
        }
    // h1 store word positions (xor-swizzled, constant per lane)
    int pc[2][2];
    #pragma unroll
    for (int nt = 0; nt < 2; nt++){
        int c0 = n0 + nt*8 + 2*tig;
        pc[nt][0] = pcol(c0) ^ xr;
        pc[nt][1] = pcol(c0+1) ^ xr;
    }

    for (int it = blockIdx.x; it < CQ/4; it += gridDim.x){
        int q0 = it * 4;
        int b  = q0 >> 12;
        const float* f1b = g_F1 + (size_t)b*NP*TOK;
        const float* xs = g_x + (size_t)b*NP;
        const float* ys = g_y + (size_t)b*NP;
        const float* zs = g_z + (size_t)b*NP;
        __syncthreads();

        // ---- stage: sj, pes (128 rows, tf32 permuted+swizzled), sA1b ----
        if (tid < 128){
            int r = tid, qq = r >> 5, k = r & 31;
            int q = q0 + qq, i = q & (NP-1);
            int j = g_idx[(size_t)q*KN + k];
            sj[qq*KN + k] = j;
            int xs_r = (r & 7) << 2;
            float rx = xs[j]-xs[i], ry = ys[j]-ys[i], rz = zs[j]-zs[i];
            unsigned* pr = pes + r*PESS;
            pr[pcol(0) ^ xs_r] = tf32c(rx);
            pr[pcol(1) ^ xs_r] = tf32c(ry);
            pr[pcol(2) ^ xs_r] = tf32c(rz);
            float rv[3] = {rx, ry, rz};
            const float fr[4] = {1.0f, 0.046415888336127795f,
                                 0.0021544346900318843f, 1.0e-4f};
            #pragma unroll
            for (int a = 0; a < 3; a++)
                #pragma unroll
                for (int f = 0; f < 4; f++){
                    float s, cc;
                    __sincosf(rv[a]*fr[f], &s, &cc);
                    pr[pcol(3 + a*8 + f)     ^ xs_r] = tf32c(s);
                    pr[pcol(3 + a*8 + 4 + f) ^ xs_r] = tf32c(cc);
                }
            #pragma unroll
            for (int d = 27; d < 32; d++) pr[pcol(d) ^ xs_r] = 0u;
        } else {
            int t2 = tid - 128;
            int qq = t2 >> 5, e = (t2 & 31)*4;
            float4 v = *(const float4*)&g_A1b[(size_t)(q0+qq)*TOK + e];
            *(float4*)&sA1b[qq*TOK + e] = v;
        }
        __syncthreads();

        // ---- phase A: h1 = relu(pes@W1rel + F1[j] + A1b[i]) ----
        #pragma unroll 1
        for (int m = 0; m < 8; m++){
            int r0 = m*16 + g, r1 = r0 + 8, qq = m >> 1;
            const unsigned* pr0 = pes + r0*PESS;
            const unsigned* pr1 = pes + r1*PESS;
            uint4 lo0 = *(const uint4*)(pr0 + ((4*tig)      ^ xr));
            uint4 hi0 = *(const uint4*)(pr1 + ((4*tig)      ^ xr));
            uint4 lo1 = *(const uint4*)(pr0 + ((16 + 4*tig) ^ xr));
            uint4 hi1 = *(const uint4*)(pr1 + ((16 + 4*tig) ^ xr));
            int j0 = sj[qq*KN + (r0 & 31)];
            int j1 = sj[qq*KN + (r1 & 31)];
            float2 f1v[2][2], a1v[2];
            #pragma unroll
            for (int nt = 0; nt < 2; nt++){
                int c0 = n0 + nt*8 + 2*tig;
                f1v[nt][0] = *(const float2*)&f1b[(size_t)j0*TOK + c0];
                f1v[nt][1] = *(const float2*)&f1b[(size_t)j1*TOK + c0];
                a1v[nt]    = *(const float2*)&sA1b[qq*TOK + c0];
            }
            float acc[2][4] = {{0,0,0,0},{0,0,0,0}};
            #pragma unroll
            for (int nt = 0; nt < 2; nt++){
                mma8(acc[nt], lo0.x, hi0.x, lo0.z, hi0.z, bw1[0][nt][0], bw1[0][nt][1]);
                mma8(acc[nt], lo0.y, hi0.y, lo0.w, hi0.w, bw1[1][nt][0], bw1[1][nt][1]);
                mma8(acc[nt], lo1.x, hi1.x, lo1.z, hi1.z, bw1[2][nt][0], bw1[2][nt][1]);
                mma8(acc[nt], lo1.y, hi1.y, lo1.w, hi1.w, bw1[3][nt][0], bw1[3][nt][1]);
            }
            #pragma unroll
            for (int nt = 0; nt < 2; nt++){
                h1s[r0*H1S + pc[nt][0]] = tf32c(fmaxf(acc[nt][0] + f1v[nt][0].x + a1v[nt].x, 0.f));
                h1s[r0*H1S + pc[nt][1]] = tf32c(fmaxf(acc[nt][1] + f1v[nt][0].y + a1v[nt].y, 0.f));
                h1s[r1*H1S + pc[nt][0]] = tf32c(fmaxf(acc[nt][2] + f1v[nt][1].x + a1v[nt].x, 0.f));
                h1s[r1*H1S + pc[nt][1]] = tf32c(fmaxf(acc[nt][3] + f1v[nt][1].y + a1v[nt].y, 0.f));
            }
        }
        __syncthreads();

        // ---- phase B: h2 = h1 @ W2, full k per warp; max into sbmax ----
        #pragma unroll 1
        for (int m = 0; m < 8; m++){
            int r0 = m*16 + g;
            const unsigned* a0p = h1s + r0*H1S;
            const unsigned* a1p = a0p + 8*H1S;
            float acc[2][4] = {{0,0,0,0},{0,0,0,0}};
            #pragma unroll
            for (int kp = 0; kp < 8; kp++){
                uint4 lo = *(const uint4*)(a0p + ((kp*16 + 4*tig) ^ xr));
                uint4 hi = *(const uint4*)(a1p + ((kp*16 + 4*tig) ^ xr));
                #pragma unroll
                for (int nt = 0; nt < 2; nt++){
                    mma8(acc[nt], lo.x, hi.x, lo.z, hi.z,
                         bw2[2*kp  ][nt][0], bw2[2*kp  ][nt][1]);
                    mma8(acc[nt], lo.y, hi.y, lo.w, hi.w,
                         bw2[2*kp+1][nt][0], bw2[2*kp+1][nt][1]);
                }
            }
            #pragma unroll
            for (int nt = 0; nt < 2; nt++){
                float m0 = fmaxf(acc[nt][0], acc[nt][2]);
                float m1 = fmaxf(acc[nt][1], acc[nt][3]);
                #pragma unroll
                for (int off = 16; off >= 4; off >>= 1){
                    m0 = fmaxf(m0, __shfl_xor_sync(0xFFFFFFFFu, m0, off));
                    m1 = fmaxf(m1, __shfl_xor_sync(0xFFFFFFFFu, m1, off));
                }
                if (lane < 4){
                    int cB = n0 + nt*8 + 2*tig;
                    atomicMax(&sbmax[b*TOK + cB    ], f2ord(m0));
                    atomicMax(&sbmax[b*TOK + cB + 1], f2ord(m1));
                }
            }
        }
    }
    __syncthreads();
    atomicMax(&g_gmax[tid], sbmax[tid]);
}

// ---------------------------------------------------------------------------
// Final: g = max + b2 ; g = relu(g@W3+b3) ; out = g@W4+b4   (fp32)
// ---------------------------------------------------------------------------
__global__ __launch_bounds__(512)
void final_kernel(const float* __restrict__ b2,
                  const float* __restrict__ W3,
                  const float* __restrict__ b3,
                  const float* __restrict__ W4,
                  const float* __restrict__ b4,
                  float* __restrict__ out){
    int b = blockIdx.x;
    int c = threadIdx.x & 127, p = threadIdx.x >> 7;   // p in 0..3
    __shared__ float gbuf[TOK], hbuf[TOK], part[4][TOK];
    if (p == 0) gbuf[c] = ord2f(g_gmax[b*TOK + c]) + b2[c];
    __syncthreads();
    float acc = 0.f;
    #pragma unroll 8
    for (int d = p*32; d < p*32 + 32; d++) acc += gbuf[d] * W3[d*TOK + c];
    part[p][c] = acc;
    __syncthreads();
    if (p == 0)
        hbuf[c] = fmaxf(part[0][c]+part[1][c]+part[2][c]+part[3][c]+b3[c], 0.f);
    __syncthreads();
    acc = 0.f;
    #pragma unroll 8
    for (int d = p*32; d < p*32 + 32; d++) acc += hbuf[d] * W4[d*TOK + c];
    part[p][c] = acc;
    __syncthreads();
    if (p == 0)
        out[b*TOK + c] = part[0][c]+part[1][c]+part[2][c]+part[3][c]+b4[c];
}

// ---------------------------------------------------------------------------
extern "C" void kernel_launch(void* const* d_in, const int* in_sizes, int n_in,
                              void* d_out, int out_size){
    const float* xyz  = (const float*)d_in[0];
    const float* feat = (const float*)d_in[1];
    const float* W1   = (const float*)d_in[2];
    const float* b1   = (const float*)d_in[3];
    const float* W2   = (const float*)d_in[4];
    const float* b2   = (const float*)d_in[5];
    const float* W3   = (const float*)d_in[6];
    const float* b3   = (const float*)d_in[7];
    const float* W4   = (const float*)d_in[8];
    const float* b4   = (const float*)d_in[9];
    float* out = (float*)d_out;

    const int PRE_SMEM  = (64*TOK + 96*TOK + TOK + 4*64 + 4*96 + 12)*4;
    const int MAIN_SMEM = (128*H1S + 128*PESS)*4 + 4*TOK*4 + 4*KN*4 + BN*TOK*4;
    cudaFuncSetAttribute(precompute_kernel,
                         cudaFuncAttributeMaxDynamicSharedMemorySize, PRE_SMEM);
    cudaFuncSetAttribute(main_kernel,
                         cudaFuncAttributeMaxDynamicSharedMemorySize, MAIN_SMEM);

    transpose_kernel<<<(CQ+1023)/1024, 1024>>>(xyz);
    precompute_kernel<<<296, 256, PRE_SMEM>>>(xyz, feat, W1, b1);
    neighbor_kernel<<<CQ/8, 256>>>();
    main_kernel<<<296, 256, MAIN_SMEM>>>(W1, W2);
    final_kernel<<<BN, 512>>>(b2, W3, b3, W4, b4, out);
}

// round 12
// speedup vs baseline: 1.8205x; 1.2311x over previous
#include <cuda_runtime.h>
#include <cuda_fp16.h>
#include <cstdint>

#define BN  2
#define NP  4096
#define KN  32
#define TOK 128
#define CQ  (BN*NP)
#define RAD2 (0.16f*0.16f)
#define H1S 72    // h1 fp16 row stride (words = fp16x2)
#define PESS 48   // pes smem row stride (words)

// Scratch (no allocations allowed)
__device__ float    g_F1 [CQ*TOK];   // feature @ W1[0:64]
__device__ float    g_A1b[CQ*TOK];   // abs_pe @ W1[91:187] + b1
__device__ int      g_idx[CQ*KN];
__device__ unsigned g_gmax[BN*TOK];
__device__ float    g_x[CQ], g_y[CQ], g_z[CQ];   // SoA xyz

__device__ __forceinline__ unsigned f2ord(float f){
    unsigned u = __float_as_uint(f);
    return (u & 0x80000000u) ? ~u : (u | 0x80000000u);
}
__device__ __forceinline__ float ord2f(unsigned u){
    return __uint_as_float((u & 0x80000000u) ? (u ^ 0x80000000u) : ~u);
}
__device__ __forceinline__ unsigned tf32c(float f){
    unsigned u; asm("cvt.rna.tf32.f32 %0, %1;" : "=r"(u) : "f"(f)); return u;
}
__device__ __forceinline__ unsigned packh2(float lo, float hi){
    unsigned u; asm("cvt.rn.f16x2.f32 %0, %1, %2;" : "=r"(u) : "f"(hi), "f"(lo));
    return u;
}
// permuted column index for tf32 pes (validated R2-R9)
__device__ __host__ __forceinline__ int pcol(int c){
    int t = (c >> 3) & 1;
    int pos = 2*(c & 3) + ((c >> 2) & 1);
    return (c & ~15) + pos*2 + t;
}
__device__ __forceinline__ void mma8(float* c, unsigned a0, unsigned a1,
                                     unsigned a2, unsigned a3,
                                     unsigned b0, unsigned b1){
    asm volatile("mma.sync.aligned.m16n8k8.row.col.f32.tf32.tf32.f32 "
        "{%0,%1,%2,%3},{%4,%5,%6,%7},{%8,%9},{%0,%1,%2,%3};"
        : "+f"(c[0]), "+f"(c[1]), "+f"(c[2]), "+f"(c[3])
        : "r"(a0), "r"(a1), "r"(a2), "r"(a3), "r"(b0), "r"(b1));
}
__device__ __forceinline__ void mma16(float* c, unsigned a0, unsigned a1,
                                      unsigned a2, unsigned a3,
                                      unsigned b0, unsigned b1){
    asm volatile("mma.sync.aligned.m16n8k16.row.col.f32.f16.f16.f32 "
        "{%0,%1,%2,%3},{%4,%5,%6,%7},{%8,%9},{%0,%1,%2,%3};"
        : "+f"(c[0]), "+f"(c[1]), "+f"(c[2]), "+f"(c[3])
        : "r"(a0), "r"(a1), "r"(a2), "r"(a3), "r"(b0), "r"(b1));
}

// ---------------------------------------------------------------------------
// Transpose xyz AoS -> SoA, init g_gmax
// ---------------------------------------------------------------------------
__global__ void transpose_kernel(const float* __restrict__ xyz){
    int i = blockIdx.x*blockDim.x + threadIdx.x;
    if (i < CQ){
        g_x[i] = xyz[i*3];
        g_y[i] = xyz[i*3+1];
        g_z[i] = xyz[i*3+2];
    }
    if (i < BN*TOK) g_gmax[i] = 0u;
}

// ---------------------------------------------------------------------------
// Precompute (weight-stationary): W1 rows [0:64) + [91:187) in smem once per
// block; grid-stride over point groups of 4.
// ---------------------------------------------------------------------------
__global__ __launch_bounds__(256)
void precompute_kernel(const float* __restrict__ xyz,
                       const float* __restrict__ feat,
                       const float* __restrict__ W1,
                       const float* __restrict__ b1){
    extern __shared__ float psm[];
    float* W1f = psm;                 // 64*128
    float* W1a = W1f + 64*TOK;        // 96*128
    float* b1s = W1a + 96*TOK;        // 128
    float* sfb = b1s + TOK;           // 4*64
    float* spb = sfb + 4*64;          // 4*96
    float* sx  = spb + 4*96;          // 12
    const int tid = threadIdx.x;

    for (int t = tid; t < 64*TOK/4; t += 256)
        ((float4*)W1f)[t] = ((const float4*)W1)[t];
    for (int t = tid; t < 96*TOK/4; t += 256)
        ((float4*)W1a)[t] = ((const float4*)(W1 + 91*TOK))[t];
    if (tid < TOK) b1s[tid] = b1[tid];

    const int c  = tid & 127;
    const int ph = tid >> 7;       // 0..1 -> rows {2ph, 2ph+1}

    for (int rr = blockIdx.x; rr < CQ/4; rr += gridDim.x){
        int r0 = rr*4;
        __syncthreads();
        if (tid < 12) sx[tid] = xyz[r0*3 + tid];
        {   // sf: 4 rows x 64 (256 threads cover exactly)
            int p = tid >> 6, d = tid & 63;
            sfb[p*64 + d] = feat[(size_t)(r0+p)*64 + d];
        }
        __syncthreads();
        for (int t = tid; t < 384; t += 256){
            int p = t / 96, cc = t % 96;
            int a = cc >> 5, kk = (cc & 31) & 15;
            float f = __expf(-0.6140226914886731f * (float)kk);
            float ang = sx[p*3 + a] * f;
            spb[p*96 + cc] = ((cc & 31) < 16) ? __sinf(ang) : __cosf(ang);
        }
        __syncthreads();
        float aF0 = 0.f, aF1 = 0.f;
        float aA0 = b1s[c], aA1 = aA0;
        const float* sf0 = sfb + (2*ph  )*64;
        const float* sf1 = sfb + (2*ph+1)*64;
        const float* sp0 = spb + (2*ph  )*96;
        const float* sp1 = spb + (2*ph+1)*96;
        #pragma unroll 16
        for (int d = 0; d < 64; d++){
            float wv = W1f[d*TOK + c];
            aF0 += sf0[d] * wv;
            aF1 += sf1[d] * wv;
        }
        #pragma unroll 16
        for (int d = 0; d < 96; d++){
            float wv = W1a[d*TOK + c];
            aA0 += sp0[d] * wv;
            aA1 += sp1[d] * wv;
        }
        g_F1 [(size_t)(r0+2*ph  )*TOK + c] = aF0;
        g_F1 [(size_t)(r0+2*ph+1)*TOK + c] = aF1;
        g_A1b[(size_t)(r0+2*ph  )*TOK + c] = aA0;
        g_A1b[(size_t)(r0+2*ph+1)*TOK + c] = aA1;
    }
}

// ---------------------------------------------------------------------------
// Ball query (SoA): first KN ascending indices with d2 <= r^2
// ---------------------------------------------------------------------------
__global__ __launch_bounds__(256)
void neighbor_kernel(){
    int gtid = blockIdx.x*blockDim.x + threadIdx.x;
    int w    = gtid >> 5;
    int lane = threadIdx.x & 31;
    if (w >= CQ) return;
    int b = w >> 12, i = w & (NP-1);
    const float* xs = g_x + (size_t)b*NP;
    const float* ys = g_y + (size_t)b*NP;
    const float* zs = g_z + (size_t)b*NP;
    float cx = xs[i], cy = ys[i], cz = zs[i];
    __shared__ int s_idx[8][KN];
    int wl = threadIdx.x >> 5;
    int count = 0;
    for (int base = 0; base < NP && count < KN; base += 32){
        int j = base + lane;
        float dx = xs[j]-cx, dy = ys[j]-cy, dz = zs[j]-cz;
        float d2 = dx*dx + dy*dy + dz*dz;
        bool hit = (d2 <= RAD2);
        unsigned m = __ballot_sync(0xFFFFFFFFu, hit);
        int pos = count + __popc(m & ((1u << lane) - 1u));
        if (hit && pos < KN) s_idx[wl][pos] = j;
        count += __popc(m);
    }
    __syncwarp();
    int stored = count < KN ? count : KN;
    int first  = s_idx[wl][0];
    int v = (lane < stored) ? s_idx[wl][lane] : first;
    g_idx[(size_t)w*KN + lane] = v;
}

// ---------------------------------------------------------------------------
// Main kernel: 256 threads, 2 CTAs/SM, 4 queries (128 rows) per iter.
// Phase A: tf32 mma (pes, xor-swizzled) -> h1 packed fp16, stored via stmatrix.
// Phase B: fp16 m16n8k16 mma; A-frags via ldmatrix.x4 (conflict-free layout:
//          word = r*72 + 4*(chunk ^ (r&7)) -- banks enumerated, all distinct).
// ---------------------------------------------------------------------------
__global__ __launch_bounds__(256, 2)
void main_kernel(const float* __restrict__ W1,
                 const float* __restrict__ W2){
    extern __shared__ unsigned char smraw[];
    unsigned* h1s  = (unsigned*)smraw;               // 128*72 words (fp16x2)
    unsigned* pes  = h1s + 128*H1S;                  // 128*48
    float*    sA1b = (float*)(pes + 128*PESS);       // 4*128
    int*      sj   = (int*)(sA1b + 4*TOK);           // 4*32
    unsigned* sbmax= (unsigned*)(sj + 4*KN);         // 2*128

    const int tid  = threadIdx.x;
    const int w    = tid >> 5;       // 0..7
    const int lane = tid & 31;
    const int g    = lane >> 2;
    const int tig  = lane & 3;
    const int n0   = w * 16;         // 16 cols per warp
    const int xr   = g << 2;         // pes row-xor (r&7 == g for phase A rows)

    // ldmatrix/stmatrix lane geometry
    const int tt    = lane >> 3;     // tile 0..3
    const int j8    = lane & 7;      // row within tile
    const int thalf = tt >> 1;       // chunk parity
    const int rbase = (tt & 1)*8 + j8;
    const unsigned h1b = (unsigned)__cvta_generic_to_shared(h1s);
    // stmatrix word offset (constant per lane; chunk q = 2w+thalf)
    const int sword = rbase*H1S + 4*(((2*w + thalf) ^ j8));

    sbmax[tid] = 0u;

    // W2 B-frags (fp16): 8 k16-tiles x 2 n-tiles x 2 regs
    unsigned bw2h[8][2][2];
    #pragma unroll
    for (int kt = 0; kt < 8; kt++)
        #pragma unroll
        for (int nt = 0; nt < 2; nt++){
            int col = n0 + nt*8 + g;
            int k0 = 16*kt + 2*tig;
            bw2h[kt][nt][0] = packh2(W2[(k0    )*TOK + col], W2[(k0+1)*TOK + col]);
            bw2h[kt][nt][1] = packh2(W2[(k0 + 8)*TOK + col], W2[(k0+9)*TOK + col]);
        }
    // W1rel B-frags (tf32): 4 k8-tiles x 2 n-tiles
    unsigned bw1[4][2][2];
    #pragma unroll
    for (int kt = 0; kt < 4; kt++)
        #pragma unroll
        for (int nt = 0; nt < 2; nt++){
            int col = n0 + nt*8 + g;
            int k0 = kt*8 + tig, k1 = k0 + 4;
            bw1[kt][nt][0] = (k0 < 27) ? tf32c(W1[(64+k0)*TOK + col]) : 0u;
            bw1[kt][nt][1] = (k1 < 27) ? tf32c(W1[(64+k1)*TOK + col]) : 0u;
        }

    for (int it = blockIdx.x; it < CQ/4; it += gridDim.x){
        int q0 = it * 4;
        int b  = q0 >> 12;
        const float* f1b = g_F1 + (size_t)b*NP*TOK;
        const float* xs = g_x + (size_t)b*NP;
        const float* ys = g_y + (size_t)b*NP;
        const float* zs = g_z + (size_t)b*NP;
        __syncthreads();

        // ---- stage: sj, pes (128 rows, tf32 permuted+swizzled), sA1b ----
        if (tid < 128){
            int r = tid, qq = r >> 5, k = r & 31;
            int q = q0 + qq, i = q & (NP-1);
            int j = g_idx[(size_t)q*KN + k];
            sj[qq*KN + k] = j;
            int xs_r = (r & 7) << 2;
            float rx = xs[j]-xs[i], ry = ys[j]-ys[i], rz = zs[j]-zs[i];
            unsigned* pr = pes + r*PESS;
            pr[pcol(0) ^ xs_r] = tf32c(rx);
            pr[pcol(1) ^ xs_r] = tf32c(ry);
            pr[pcol(2) ^ xs_r] = tf32c(rz);
            float rv[3] = {rx, ry, rz};
            const float fr[4] = {1.0f, 0.046415888336127795f,
                                 0.0021544346900318843f, 1.0e-4f};
            #pragma unroll
            for (int a = 0; a < 3; a++)
                #pragma unroll
                for (int f = 0; f < 4; f++){
                    float s, cc;
                    __sincosf(rv[a]*fr[f], &s, &cc);
                    pr[pcol(3 + a*8 + f)     ^ xs_r] = tf32c(s);
                    pr[pcol(3 + a*8 + 4 + f) ^ xs_r] = tf32c(cc);
                }
            #pragma unroll
            for (int d = 27; d < 32; d++) pr[pcol(d) ^ xs_r] = 0u;
        } else {
            int t2 = tid - 128;
            int qq = t2 >> 5, e = (t2 & 31)*4;
            float4 v = *(const float4*)&g_A1b[(size_t)(q0+qq)*TOK + e];
            *(float4*)&sA1b[qq*TOK + e] = v;
        }
        __syncthreads();

        // ---- phase A: h1 = relu(pes@W1rel + F1[j] + A1b[i]) -> fp16 stmatrix ----
        #pragma unroll 1
        for (int m = 0; m < 8; m++){
            int r0 = m*16 + g, r1 = r0 + 8, qq = m >> 1;
            const unsigned* pr0 = pes + r0*PESS;
            const unsigned* pr1 = pes + r1*PESS;
            uint4 lo0 = *(const uint4*)(pr0 + ((4*tig)      ^ xr));
            uint4 hi0 = *(const uint4*)(pr1 + ((4*tig)      ^ xr));
            uint4 lo1 = *(const uint4*)(pr0 + ((16 + 4*tig) ^ xr));
            uint4 hi1 = *(const uint4*)(pr1 + ((16 + 4*tig) ^ xr));
            int j0 = sj[qq*KN + (r0 & 31)];
            int j1 = sj[qq*KN + (r1 & 31)];
            float2 f1v[2][2], a1v[2];
            #pragma unroll
            for (int nt = 0; nt < 2; nt++){
                int c0 = n0 + nt*8 + 2*tig;
                f1v[nt][0] = *(const float2*)&f1b[(size_t)j0*TOK + c0];
                f1v[nt][1] = *(const float2*)&f1b[(size_t)j1*TOK + c0];
                a1v[nt]    = *(const float2*)&sA1b[qq*TOK + c0];
            }
            float acc[2][4] = {{0,0,0,0},{0,0,0,0}};
            #pragma unroll
            for (int nt = 0; nt < 2; nt++){
                mma8(acc[nt], lo0.x, hi0.x, lo0.z, hi0.z, bw1[0][nt][0], bw1[0][nt][1]);
                mma8(acc[nt], lo0.y, hi0.y, lo0.w, hi0.w, bw1[1][nt][0], bw1[1][nt][1]);
                mma8(acc[nt], lo1.x, hi1.x, lo1.z, hi1.z, bw1[2][nt][0], bw1[2][nt][1]);
                mma8(acc[nt], lo1.y, hi1.y, lo1.w, hi1.w, bw1[3][nt][0], bw1[3][nt][1]);
            }
            // pack to fp16x2 and stmatrix (T0:rows r0/nt0, T1:r1/nt0, T2:r0/nt1, T3:r1/nt1)
            unsigned v0 = packh2(fmaxf(acc[0][0]+f1v[0][0].x+a1v[0].x, 0.f),
                                 fmaxf(acc[0][1]+f1v[0][0].y+a1v[0].y, 0.f));
            unsigned v1 = packh2(fmaxf(acc[0][2]+f1v[0][1].x+a1v[0].x, 0.f),
                                 fmaxf(acc[0][3]+f1v[0][1].y+a1v[0].y, 0.f));
            unsigned v2 = packh2(fmaxf(acc[1][0]+f1v[1][0].x+a1v[1].x, 0.f),
                                 fmaxf(acc[1][1]+f1v[1][0].y+a1v[1].y, 0.f));
            unsigned v3 = packh2(fmaxf(acc[1][2]+f1v[1][1].x+a1v[1].x, 0.f),
                                 fmaxf(acc[1][3]+f1v[1][1].y+a1v[1].y, 0.f));
            unsigned adr = h1b + ((m*16*H1S + sword) << 2);
            asm volatile("stmatrix.sync.aligned.m8n8.x4.shared.b16 [%0], {%1,%2,%3,%4};"
                         :: "r"(adr), "r"(v0), "r"(v1), "r"(v2), "r"(v3) : "memory");
        }
        __syncthreads();

        // ---- phase B: h2 = h1 @ W2 (fp16 k16), max into sbmax ----
        #pragma unroll 1
        for (int m = 0; m < 8; m++){
            float acc[2][4] = {{0,0,0,0},{0,0,0,0}};
            #pragma unroll
            for (int kt = 0; kt < 8; kt++){
                unsigned a0, a1, a2, a3;
                unsigned adr = h1b +
                    ((m*16*H1S + rbase*H1S + 4*(((2*kt + thalf) ^ j8))) << 2);
                asm volatile("ldmatrix.sync.aligned.m8n8.x4.shared.b16 {%0,%1,%2,%3}, [%4];"
                             : "=r"(a0), "=r"(a1), "=r"(a2), "=r"(a3) : "r"(adr));
                mma16(acc[0], a0, a1, a2, a3, bw2h[kt][0][0], bw2h[kt][0][1]);
                mma16(acc[1], a0, a1, a2, a3, bw2h[kt][1][0], bw2h[kt][1][1]);
            }
            #pragma unroll
            for (int nt = 0; nt < 2; nt++){
                float m0 = fmaxf(acc[nt][0], acc[nt][2]);
                float m1 = fmaxf(acc[nt][1], acc[nt][3]);
                #pragma unroll
                for (int off = 16; off >= 4; off >>= 1){
                    m0 = fmaxf(m0, __shfl_xor_sync(0xFFFFFFFFu, m0, off));
                    m1 = fmaxf(m1, __shfl_xor_sync(0xFFFFFFFFu, m1, off));
                }
                if (lane < 4){
                    int cB = n0 + nt*8 + 2*tig;
                    atomicMax(&sbmax[b*TOK + cB    ], f2ord(m0));
                    atomicMax(&sbmax[b*TOK + cB + 1], f2ord(m1));
                }
            }
        }
    }
    __syncthreads();
    atomicMax(&g_gmax[tid], sbmax[tid]);
}

// ---------------------------------------------------------------------------
// Final: g = max + b2 ; g = relu(g@W3+b3) ; out = g@W4+b4   (fp32)
// ---------------------------------------------------------------------------
__global__ __launch_bounds__(512)
void final_kernel(const float* __restrict__ b2,
                  const float* __restrict__ W3,
                  const float* __restrict__ b3,
                  const float* __restrict__ W4,
                  const float* __restrict__ b4,
                  float* __restrict__ out){
    int b = blockIdx.x;
    int c = threadIdx.x & 127, p = threadIdx.x >> 7;   // p in 0..3
    __shared__ float gbuf[TOK], hbuf[TOK], part[4][TOK];
    if (p == 0) gbuf[c] = ord2f(g_gmax[b*TOK + c]) + b2[c];
    __syncthreads();
    float acc = 0.f;
    #pragma unroll 8
    for (int d = p*32; d < p*32 + 32; d++) acc += gbuf[d] * W3[d*TOK + c];
    part[p][c] = acc;
    __syncthreads();
    if (p == 0)
        hbuf[c] = fmaxf(part[0][c]+part[1][c]+part[2][c]+part[3][c]+b3[c], 0.f);
    __syncthreads();
    acc = 0.f;
    #pragma unroll 8
    for (int d = p*32; d < p*32 + 32; d++) acc += hbuf[d] * W4[d*TOK + c];
    part[p][c] = acc;
    __syncthreads();
    if (p == 0)
        out[b*TOK + c] = part[0][c]+part[1][c]+part[2][c]+part[3][c]+b4[c];
}

// ---------------------------------------------------------------------------
extern "C" void kernel_launch(void* const* d_in, const int* in_sizes, int n_in,
                              void* d_out, int out_size){
    const float* xyz  = (const float*)d_in[0];
    const float* feat = (const float*)d_in[1];
    const float* W1   = (const float*)d_in[2];
    const float* b1   = (const float*)d_in[3];
    const float* W2   = (const float*)d_in[4];
    const float* b2   = (const float*)d_in[5];
    const float* W3   = (const float*)d_in[6];
    const float* b3   = (const float*)d_in[7];
    const float* W4   = (const float*)d_in[8];
    const float* b4   = (const float*)d_in[9];
    float* out = (float*)d_out;

    const int PRE_SMEM  = (64*TOK + 96*TOK + TOK + 4*64 + 4*96 + 12)*4;
    const int MAIN_SMEM = (128*H1S + 128*PESS)*4 + 4*TOK*4 + 4*KN*4 + BN*TOK*4;
    cudaFuncSetAttribute(precompute_kernel,
                         cudaFuncAttributeMaxDynamicSharedMemorySize, PRE_SMEM);
    cudaFuncSetAttribute(main_kernel,
                         cudaFuncAttributeMaxDynamicSharedMemorySize, MAIN_SMEM);

    transpose_kernel<<<(CQ+1023)/1024, 1024>>>(xyz);
    precompute_kernel<<<296, 256, PRE_SMEM>>>(xyz, feat, W1, b1);
    neighbor_kernel<<<CQ/8, 256>>>();
    main_kernel<<<296, 256, MAIN_SMEM>>>(W1, W2);
    final_kernel<<<BN, 512>>>(b2, W3, b3, W4, b4, out);
}

// round 13
// speedup vs baseline: 2.2409x; 1.2309x over previous
#include <cuda_runtime.h>
#include <cuda_fp16.h>
#include <cstdint>

#define BN  2
#define NP  4096
#define KN  32
#define TOK 128
#define CQ  (BN*NP)
#define RAD2 (0.16f*0.16f)
#define H1S 72    // h1 fp16 row stride (words)
#define PS2 20    // pes fp16 row stride (words) -- bank-conflict-free for ldmatrix

// Scratch (no allocations allowed)
__device__ float    g_F1 [CQ*TOK];   // feature @ W1[0:64]
__device__ float    g_A1b[CQ*TOK];   // abs_pe @ W1[91:187] + b1
__device__ int      g_idx[CQ*KN];
__device__ unsigned g_gmax[BN*TOK];
__device__ float    g_x[CQ], g_y[CQ], g_z[CQ];   // SoA xyz

__device__ __forceinline__ unsigned f2ord(float f){
    unsigned u = __float_as_uint(f);
    return (u & 0x80000000u) ? ~u : (u | 0x80000000u);
}
__device__ __forceinline__ float ord2f(unsigned u){
    return __uint_as_float((u & 0x80000000u) ? (u ^ 0x80000000u) : ~u);
}
__device__ __forceinline__ unsigned packh2(float lo, float hi){
    unsigned u; asm("cvt.rn.f16x2.f32 %0, %1, %2;" : "=r"(u) : "f"(hi), "f"(lo));
    return u;
}
__device__ __forceinline__ void mma16(float* c, unsigned a0, unsigned a1,
                                      unsigned a2, unsigned a3,
                                      unsigned b0, unsigned b1){
    asm volatile("mma.sync.aligned.m16n8k16.row.col.f32.f16.f16.f32 "
        "{%0,%1,%2,%3},{%4,%5,%6,%7},{%8,%9},{%0,%1,%2,%3};"
        : "+f"(c[0]), "+f"(c[1]), "+f"(c[2]), "+f"(c[3])
        : "r"(a0), "r"(a1), "r"(a2), "r"(a3), "r"(b0), "r"(b1));
}

// ---------------------------------------------------------------------------
// Precompute (weight-stationary) + fused transpose/init prologue.
// ---------------------------------------------------------------------------
__global__ __launch_bounds__(256)
void precompute_kernel(const float* __restrict__ xyz,
                       const float* __restrict__ feat,
                       const float* __restrict__ W1,
                       const float* __restrict__ b1){
    extern __shared__ float psm[];
    float* W1f = psm;                 // 64*128
    float* W1a = W1f + 64*TOK;        // 96*128
    float* b1s = W1a + 96*TOK;        // 128
    float* sfb = b1s + TOK;           // 4*64
    float* spb = sfb + 4*64;          // 4*96
    float* sx  = spb + 4*96;          // 12
    const int tid = threadIdx.x;

    // fused transpose + gmax init
    for (int i = blockIdx.x*256 + tid; i < CQ; i += gridDim.x*256){
        g_x[i] = xyz[i*3];
        g_y[i] = xyz[i*3+1];
        g_z[i] = xyz[i*3+2];
    }
    if (blockIdx.x == 0) g_gmax[tid] = 0u;   // 256 == BN*TOK

    for (int t = tid; t < 64*TOK/4; t += 256)
        ((float4*)W1f)[t] = ((const float4*)W1)[t];
    for (int t = tid; t < 96*TOK/4; t += 256)
        ((float4*)W1a)[t] = ((const float4*)(W1 + 91*TOK))[t];
    if (tid < TOK) b1s[tid] = b1[tid];

    const int c  = tid & 127;
    const int ph = tid >> 7;       // 0..1 -> rows {2ph, 2ph+1}

    for (int rr = blockIdx.x; rr < CQ/4; rr += gridDim.x){
        int r0 = rr*4;
        __syncthreads();
        if (tid < 12) sx[tid] = xyz[r0*3 + tid];
        {
            int p = tid >> 6, d = tid & 63;
            sfb[p*64 + d] = feat[(size_t)(r0+p)*64 + d];
        }
        __syncthreads();
        for (int t = tid; t < 384; t += 256){
            int p = t / 96, cc = t % 96;
            int a = cc >> 5, kk = (cc & 31) & 15;
            float f = __expf(-0.6140226914886731f * (float)kk);
            float ang = sx[p*3 + a] * f;
            spb[p*96 + cc] = ((cc & 31) < 16) ? __sinf(ang) : __cosf(ang);
        }
        __syncthreads();
        float aF0 = 0.f, aF1 = 0.f;
        float aA0 = b1s[c], aA1 = aA0;
        const float* sf0 = sfb + (2*ph  )*64;
        const float* sf1 = sfb + (2*ph+1)*64;
        const float* sp0 = spb + (2*ph  )*96;
        const float* sp1 = spb + (2*ph+1)*96;
        #pragma unroll 16
        for (int d = 0; d < 64; d++){
            float wv = W1f[d*TOK + c];
            aF0 += sf0[d] * wv;
            aF1 += sf1[d] * wv;
        }
        #pragma unroll 16
        for (int d = 0; d < 96; d++){
            float wv = W1a[d*TOK + c];
            aA0 += sp0[d] * wv;
            aA1 += sp1[d] * wv;
        }
        g_F1 [(size_t)(r0+2*ph  )*TOK + c] = aF0;
        g_F1 [(size_t)(r0+2*ph+1)*TOK + c] = aF1;
        g_A1b[(size_t)(r0+2*ph  )*TOK + c] = aA0;
        g_A1b[(size_t)(r0+2*ph+1)*TOK + c] = aA1;
    }
}

// ---------------------------------------------------------------------------
// Ball query (SoA, float4 x 128-point sweeps): first KN ascending idx, d2<=r^2
// ---------------------------------------------------------------------------
__global__ __launch_bounds__(256)
void neighbor_kernel(){
    int gtid = blockIdx.x*blockDim.x + threadIdx.x;
    int w    = gtid >> 5;
    int lane = threadIdx.x & 31;
    if (w >= CQ) return;
    int b = w >> 12, i = w & (NP-1);
    const float* xs = g_x + (size_t)b*NP;
    const float* ys = g_y + (size_t)b*NP;
    const float* zs = g_z + (size_t)b*NP;
    float cx = xs[i], cy = ys[i], cz = zs[i];
    __shared__ int s_idx[8][KN];
    int wl = threadIdx.x >> 5;
    int count = 0;
    for (int base = 0; base < NP && count < KN; base += 128){
        int j0 = base + lane*4;
        float4 xv = *(const float4*)(xs + j0);
        float4 yv = *(const float4*)(ys + j0);
        float4 zv = *(const float4*)(zs + j0);
        float dx, dy, dz;
        dx = xv.x-cx; dy = yv.x-cy; dz = zv.x-cz;
        bool h0 = (dx*dx + dy*dy + dz*dz) <= RAD2;
        dx = xv.y-cx; dy = yv.y-cy; dz = zv.y-cz;
        bool h1 = (dx*dx + dy*dy + dz*dz) <= RAD2;
        dx = xv.z-cx; dy = yv.z-cy; dz = zv.z-cz;
        bool h2 = (dx*dx + dy*dy + dz*dz) <= RAD2;
        dx = xv.w-cx; dy = yv.w-cy; dz = zv.w-cz;
        bool h3 = (dx*dx + dy*dy + dz*dz) <= RAD2;
        int nl = (int)h0 + (int)h1 + (int)h2 + (int)h3;
        int pre = nl;
        #pragma unroll
        for (int off = 1; off < 32; off <<= 1){
            int t = __shfl_up_sync(0xFFFFFFFFu, pre, off);
            if (lane >= off) pre += t;
        }
        int pos = count + pre - nl;
        if (h0){ if (pos < KN) s_idx[wl][pos] = j0;     pos++; }
        if (h1){ if (pos < KN) s_idx[wl][pos] = j0 + 1; pos++; }
        if (h2){ if (pos < KN) s_idx[wl][pos] = j0 + 2; pos++; }
        if (h3){ if (pos < KN) s_idx[wl][pos] = j0 + 3; pos++; }
        count += __shfl_sync(0xFFFFFFFFu, pre, 31);
    }
    __syncwarp();
    int stored = count < KN ? count : KN;
    int first  = s_idx[wl][0];
    int v = (lane < stored) ? s_idx[wl][lane] : first;
    g_idx[(size_t)w*KN + lane] = v;
}

// ---------------------------------------------------------------------------
// Main kernel: 256 threads, 2 CTAs/SM, 4 queries (128 rows) per iter.
// Phase A: fp16 m16n8k16 mma (pes fp16, stride-20 conflict-free ldmatrix)
//          -> h1 fp16 via stmatrix.
// Phase B: fp16 m16n8k16 mma; h1 A-frags via ldmatrix (xor layout, R11).
// ---------------------------------------------------------------------------
__global__ __launch_bounds__(256, 2)
void main_kernel(const float* __restrict__ W1,
                 const float* __restrict__ W2){
    extern __shared__ unsigned char smraw[];
    unsigned* h1s  = (unsigned*)smraw;               // 128*72 words (fp16x2)
    unsigned* pes  = h1s + 128*H1S;                  // 128*20 words (fp16x2)
    float*    sA1b = (float*)(pes + 128*PS2);        // 4*128
    int*      sj   = (int*)(sA1b + 4*TOK);           // 4*32
    unsigned* sbmax= (unsigned*)(sj + 4*KN);         // 2*128

    const int tid  = threadIdx.x;
    const int w    = tid >> 5;       // 0..7
    const int lane = tid & 31;
    const int g    = lane >> 2;
    const int tig  = lane & 3;
    const int n0   = w * 16;         // 16 cols per warp

    // ldmatrix/stmatrix lane geometry
    const int tt    = lane >> 3;     // tile 0..3
    const int j8    = lane & 7;      // row within tile
    const int thalf = tt >> 1;       // chunk parity
    const int rbase = (tt & 1)*8 + j8;
    const unsigned h1b  = (unsigned)__cvta_generic_to_shared(h1s);
    const unsigned pesb = (unsigned)__cvta_generic_to_shared(pes);
    const int sword = rbase*H1S + 4*(((2*w + thalf) ^ j8));  // h1 stmatrix word

    sbmax[tid] = 0u;

    // W2 B-frags (fp16): 8 k16-tiles x 2 n-tiles x 2 regs
    unsigned bw2h[8][2][2];
    #pragma unroll
    for (int kt = 0; kt < 8; kt++)
        #pragma unroll
        for (int nt = 0; nt < 2; nt++){
            int col = n0 + nt*8 + g;
            int k0 = 16*kt + 2*tig;
            bw2h[kt][nt][0] = packh2(W2[(k0    )*TOK + col], W2[(k0+1)*TOK + col]);
            bw2h[kt][nt][1] = packh2(W2[(k0 + 8)*TOK + col], W2[(k0+9)*TOK + col]);
        }
    // W1rel B-frags (fp16): 2 k16-tiles x 2 n-tiles (k>=27 zero)
    unsigned bw1h[2][2][2];
    #pragma unroll
    for (int kt = 0; kt < 2; kt++)
        #pragma unroll
        for (int nt = 0; nt < 2; nt++){
            int col = n0 + nt*8 + g;
            int k0 = 16*kt + 2*tig;
            float v00 = (k0   < 27) ? W1[(64+k0  )*TOK + col] : 0.f;
            float v01 = (k0+1 < 27) ? W1[(64+k0+1)*TOK + col] : 0.f;
            float v10 = (k0+8 < 27) ? W1[(64+k0+8)*TOK + col] : 0.f;
            float v11 = (k0+9 < 27) ? W1[(64+k0+9)*TOK + col] : 0.f;
            bw1h[kt][nt][0] = packh2(v00, v01);
            bw1h[kt][nt][1] = packh2(v10, v11);
        }

    for (int it = blockIdx.x; it < CQ/4; it += gridDim.x){
        int q0 = it * 4;
        int b  = q0 >> 12;
        const float* f1b = g_F1 + (size_t)b*NP*TOK;
        const float* xs = g_x + (size_t)b*NP;
        const float* ys = g_y + (size_t)b*NP;
        const float* zs = g_z + (size_t)b*NP;
        __syncthreads();

        // ---- stage: sj, pes (fp16, linear stride-20 rows), sA1b ----
        if (tid < 128){
            int r = tid, qq = r >> 5, k = r & 31;
            int q = q0 + qq, i = q & (NP-1);
            int j = g_idx[(size_t)q*KN + k];
            sj[qq*KN + k] = j;
            float vals[27];
            vals[0] = xs[j]-xs[i]; vals[1] = ys[j]-ys[i]; vals[2] = zs[j]-zs[i];
            const float fr[4] = {1.0f, 0.046415888336127795f,
                                 0.0021544346900318843f, 1.0e-4f};
            #pragma unroll
            for (int a = 0; a < 3; a++)
                #pragma unroll
                for (int f = 0; f < 4; f++){
                    float s, cc;
                    __sincosf(vals[a]*fr[f], &s, &cc);
                    vals[3 + a*8 + f]     = s;
                    vals[3 + a*8 + 4 + f] = cc;
                }
            unsigned* pr = pes + r*PS2;
            #pragma unroll
            for (int d = 0; d < 13; d++)
                pr[d] = packh2(vals[2*d], vals[2*d+1]);
            pr[13] = packh2(vals[26], 0.f);
            pr[14] = 0u; pr[15] = 0u;
        } else {
            int t2 = tid - 128;
            int qq = t2 >> 5, e = (t2 & 31)*4;
            float4 v = *(const float4*)&g_A1b[(size_t)(q0+qq)*TOK + e];
            *(float4*)&sA1b[qq*TOK + e] = v;
        }
        __syncthreads();

        // ---- phase A: h1 = relu(pes@W1rel + F1[j] + A1b[i]) -> fp16 stmatrix ----
        #pragma unroll 1
        for (int m = 0; m < 8; m++){
            int r0 = m*16 + g, r1 = r0 + 8, qq = m >> 1;
            int j0 = sj[qq*KN + (r0 & 31)];
            int j1 = sj[qq*KN + (r1 & 31)];
            float2 f1v[2][2], a1v[2];
            #pragma unroll
            for (int nt = 0; nt < 2; nt++){
                int c0 = n0 + nt*8 + 2*tig;
                f1v[nt][0] = *(const float2*)&f1b[(size_t)j0*TOK + c0];
                f1v[nt][1] = *(const float2*)&f1b[(size_t)j1*TOK + c0];
                a1v[nt]    = *(const float2*)&sA1b[qq*TOK + c0];
            }
            float acc[2][4] = {{0,0,0,0},{0,0,0,0}};
            #pragma unroll
            for (int kt = 0; kt < 2; kt++){
                unsigned a0, a1, a2, a3;
                unsigned adr = pesb +
                    (((m*16 + rbase)*PS2 + 4*(2*kt + thalf)) << 2);
                asm volatile("ldmatrix.sync.aligned.m8n8.x4.shared.b16 {%0,%1,%2,%3}, [%4];"
                             : "=r"(a0), "=r"(a1), "=r"(a2), "=r"(a3) : "r"(adr));
                mma16(acc[0], a0, a1, a2, a3, bw1h[kt][0][0], bw1h[kt][0][1]);
                mma16(acc[1], a0, a1, a2, a3, bw1h[kt][1][0], bw1h[kt][1][1]);
            }
            unsigned v0 = packh2(fmaxf(acc[0][0]+f1v[0][0].x+a1v[0].x, 0.f),
                                 fmaxf(acc[0][1]+f1v[0][0].y+a1v[0].y, 0.f));
            unsigned v1 = packh2(fmaxf(acc[0][2]+f1v[0][1].x+a1v[0].x, 0.f),
                                 fmaxf(acc[0][3]+f1v[0][1].y+a1v[0].y, 0.f));
            unsigned v2 = packh2(fmaxf(acc[1][0]+f1v[1][0].x+a1v[1].x, 0.f),
                                 fmaxf(acc[1][1]+f1v[1][0].y+a1v[1].y, 0.f));
            unsigned v3 = packh2(fmaxf(acc[1][2]+f1v[1][1].x+a1v[1].x, 0.f),
                                 fmaxf(acc[1][3]+f1v[1][1].y+a1v[1].y, 0.f));
            unsigned adr = h1b + ((m*16*H1S + sword) << 2);
            asm volatile("stmatrix.sync.aligned.m8n8.x4.shared.b16 [%0], {%1,%2,%3,%4};"
                         :: "r"(adr), "r"(v0), "r"(v1), "r"(v2), "r"(v3) : "memory");
        }
        __syncthreads();

        // ---- phase B: h2 = h1 @ W2 (fp16 k16), max into sbmax ----
        #pragma unroll 1
        for (int m = 0; m < 8; m++){
            float acc[2][4] = {{0,0,0,0},{0,0,0,0}};
            #pragma unroll
            for (int kt = 0; kt < 8; kt++){
                unsigned a0, a1, a2, a3;
                unsigned adr = h1b +
                    ((m*16*H1S + rbase*H1S + 4*(((2*kt + thalf) ^ j8))) << 2);
                asm volatile("ldmatrix.sync.aligned.m8n8.x4.shared.b16 {%0,%1,%2,%3}, [%4];"
                             : "=r"(a0), "=r"(a1), "=r"(a2), "=r"(a3) : "r"(adr));
                mma16(acc[0], a0, a1, a2, a3, bw2h[kt][0][0], bw2h[kt][0][1]);
                mma16(acc[1], a0, a1, a2, a3, bw2h[kt][1][0], bw2h[kt][1][1]);
            }
            #pragma unroll
            for (int nt = 0; nt < 2; nt++){
                float m0 = fmaxf(acc[nt][0], acc[nt][2]);
                float m1 = fmaxf(acc[nt][1], acc[nt][3]);
                #pragma unroll
                for (int off = 16; off >= 4; off >>= 1){
                    m0 = fmaxf(m0, __shfl_xor_sync(0xFFFFFFFFu, m0, off));
                    m1 = fmaxf(m1, __shfl_xor_sync(0xFFFFFFFFu, m1, off));
                }
                if (lane < 4){
                    int cB = n0 + nt*8 + 2*tig;
                    atomicMax(&sbmax[b*TOK + cB    ], f2ord(m0));
                    atomicMax(&sbmax[b*TOK + cB + 1], f2ord(m1));
                }
            }
        }
    }
    __syncthreads();
    atomicMax(&g_gmax[tid], sbmax[tid]);
}

// ---------------------------------------------------------------------------
// Final: g = max + b2 ; g = relu(g@W3+b3) ; out = g@W4+b4   (fp32)
// ---------------------------------------------------------------------------
__global__ __launch_bounds__(512)
void final_kernel(const float* __restrict__ b2,
                  const float* __restrict__ W3,
                  const float* __restrict__ b3,
                  const float* __restrict__ W4,
                  const float* __restrict__ b4,
                  float* __restrict__ out){
    int b = blockIdx.x;
    int c = threadIdx.x & 127, p = threadIdx.x >> 7;   // p in 0..3
    __shared__ float gbuf[TOK], hbuf[TOK], part[4][TOK];
    if (p == 0) gbuf[c] = ord2f(g_gmax[b*TOK + c]) + b2[c];
    __syncthreads();
    float acc = 0.f;
    #pragma unroll 8
    for (int d = p*32; d < p*32 + 32; d++) acc += gbuf[d] * W3[d*TOK + c];
    part[p][c] = acc;
    __syncthreads();
    if (p == 0)
        hbuf[c] = fmaxf(part[0][c]+part[1][c]+part[2][c]+part[3][c]+b3[c], 0.f);
    __syncthreads();
    acc = 0.f;
    #pragma unroll 8
    for (int d = p*32; d < p*32 + 32; d++) acc += hbuf[d] * W4[d*TOK + c];
    part[p][c] = acc;
    __syncthreads();
    if (p == 0)
        out[b*TOK + c] = part[0][c]+part[1][c]+part[2][c]+part[3][c]+b4[c];
}

// ---------------------------------------------------------------------------
extern "C" void kernel_launch(void* const* d_in, const int* in_sizes, int n_in,
                              void* d_out, int out_size){
    const float* xyz  = (const float*)d_in[0];
    const float* feat = (const float*)d_in[1];
    const float* W1   = (const float*)d_in[2];
    const float* b1   = (const float*)d_in[3];
    const float* W2   = (const float*)d_in[4];
    const float* b2   = (const float*)d_in[5];
    const float* W3   = (const float*)d_in[6];
    const float* b3   = (const float*)d_in[7];
    const float* W4   = (const float*)d_in[8];
    const float* b4   = (const float*)d_in[9];
    float* out = (float*)d_out;

    const int PRE_SMEM  = (64*TOK + 96*TOK + TOK + 4*64 + 4*96 + 12)*4;
    const int MAIN_SMEM = (128*H1S + 128*PS2)*4 + 4*TOK*4 + 4*KN*4 + BN*TOK*4;
    cudaFuncSetAttribute(precompute_kernel,
                         cudaFuncAttributeMaxDynamicSharedMemorySize, PRE_SMEM);
    cudaFuncSetAttribute(main_kernel,
                         cudaFuncAttributeMaxDynamicSharedMemorySize, MAIN_SMEM);

    precompute_kernel<<<296, 256, PRE_SMEM>>>(xyz, feat, W1, b1);
    neighbor_kernel<<<CQ/8, 256>>>();
    main_kernel<<<296, 256, MAIN_SMEM>>>(W1, W2);
    final_kernel<<<BN, 512>>>(b2, W3, b3, W4, b4, out);
}